// round 4
// baseline (speedup 1.0000x reference)
#include <cuda_runtime.h>
#include <cstdint>
#include <cstddef>

#define BSZ  64
#define TT   512
#define FEAT 1024
#define HID  1024
#define H3   3072
#define NBLK 128
#define SWS  1028   // smem weight row stride (floats)
#define SHS  132    // smem h row stride (floats)
#define CHK  128    // k-chunk size
#define NCH  (HID / CHK)

// Scratch for x-projections: pre[m][n], m = b*T + t, n = gate*1024 + j
__device__ float g_pre[(size_t)BSZ * TT * H3];
// Per-step scratch: (r .* h) for the hbar matmul
__device__ float g_rh[(size_t)BSZ * HID];

// grid barrier state
__device__ unsigned g_count = 0;
__device__ volatile unsigned g_gen = 0;

// ---------- Blackwell packed f32x2 helpers ----------
__device__ __forceinline__ unsigned long long ffma2(unsigned long long a,
                                                    unsigned long long b,
                                                    unsigned long long c) {
    unsigned long long d;
    asm("fma.rn.f32x2 %0, %1, %2, %3;" : "=l"(d) : "l"(a), "l"(b), "l"(c));
    return d;
}
__device__ __forceinline__ unsigned long long pk2(float x) {
    unsigned long long r;
    asm("mov.b64 %0, {%1, %1};" : "=l"(r) : "f"(x));
    return r;
}
__device__ __forceinline__ float lo32(unsigned long long v) {
    return __uint_as_float((unsigned)(v & 0xffffffffull));
}
__device__ __forceinline__ float hi32(unsigned long long v) {
    return __uint_as_float((unsigned)(v >> 32));
}
__device__ __forceinline__ unsigned long long d2l(double d) {
    return __double_as_longlong(d);
}
__device__ __forceinline__ float sigmoidf_(float v) {
    return 1.0f / (1.0f + expf(-v));
}

// ---------- cp.async helpers ----------
__device__ __forceinline__ void cpasync16(uint32_t saddr, const void* gaddr) {
    asm volatile("cp.async.cg.shared.global [%0], [%1], 16;"
                 :: "r"(saddr), "l"(gaddr));
}
__device__ __forceinline__ void cpcommit() {
    asm volatile("cp.async.commit_group;");
}
template <int N> __device__ __forceinline__ void cpwait() {
    asm volatile("cp.async.wait_group %0;" :: "n"(N));
}

// software grid sync for a co-resident grid of NBLK blocks
__device__ __forceinline__ void gsync() {
    __threadfence();
    __syncthreads();
    if (threadIdx.x == 0) {
        unsigned my = g_gen;
        if (atomicAdd(&g_count, 1) == NBLK - 1) {
            g_count = 0;
            __threadfence();
            g_gen = my + 1;
        } else {
            while (g_gen == my) __nanosleep(32);
        }
        __threadfence();
    }
    __syncthreads();
}

// stage a 64 x CHK float tile into smem (async)
__device__ __forceinline__ void stage_tile(float* dst, const float* src,
                                           long rstride, int tid) {
#pragma unroll
    for (int i = 0; i < (64 * CHK / 4) / 512; i++) {
        int idx = tid + i * 512;
        int row = idx >> 5;          // 0..63
        int kq  = idx & 31;          // float4 index within 128-float row
        uint32_t sa = (uint32_t)__cvta_generic_to_shared(dst + row * SHS + 4 * kq);
        cpasync16(sa, src + (size_t)row * rstride + 4 * kq);
    }
    cpcommit();
}

// =====================================================================
// Kernel 1: x projections.  pre[m, n] = x[m,:] @ Wg_x[:, n%1024] + bias
// =====================================================================
__global__ __launch_bounds__(256) void xproj_kernel(
    const float* __restrict__ x,
    const float* __restrict__ wz, const float* __restrict__ wr,
    const float* __restrict__ wh,
    const float* __restrict__ bz, const float* __restrict__ br,
    const float* __restrict__ bh)
{
    __shared__ float sx[64 * 68];   // [row][k]
    __shared__ float sw[32 * 68];   // [k][n]

    const int tid = threadIdx.x;
    const int n0  = blockIdx.x * 64;
    const int m0  = blockIdx.y * 64;

    const int gate = n0 >> 10;
    const int ng   = n0 & 1023;
    const float* wptr = (gate == 0) ? wz : (gate == 1) ? wr : wh;
    const float* bptr = (gate == 0) ? bz : (gate == 1) ? br : bh;

    const int c2 = tid & 15;
    const int mq = tid >> 4;

    unsigned long long acc[4][2];
#pragma unroll
    for (int u = 0; u < 4; u++) { acc[u][0] = 0ull; acc[u][1] = 0ull; }

    const int xs_kq  = tid & 7;
    const int xs_row = tid >> 3;
    const int ws_nq  = tid & 15;
    const int ws_kr  = tid >> 4;

    for (int k0 = 0; k0 < FEAT; k0 += 32) {
#pragma unroll
        for (int i = 0; i < 2; i++) {
            int row = xs_row + 32 * i;
            float4 v = *(const float4*)(x + (size_t)(m0 + row) * FEAT + k0 + 4 * xs_kq);
            *(float4*)&sx[row * 68 + 4 * xs_kq] = v;
        }
#pragma unroll
        for (int i = 0; i < 2; i++) {
            int kr = ws_kr + 16 * i;
            float4 v = *(const float4*)(wptr + (size_t)(1024 + k0 + kr) * HID + ng + 4 * ws_nq);
            *(float4*)&sw[kr * 68 + 4 * ws_nq] = v;
        }
        __syncthreads();

#pragma unroll
        for (int k = 0; k < 32; k += 4) {
            unsigned long long xp[4][4];
#pragma unroll
            for (int u = 0; u < 4; u++) {
                float4 xv = *(const float4*)&sx[(mq + 16 * u) * 68 + k];
                xp[u][0] = pk2(xv.x); xp[u][1] = pk2(xv.y);
                xp[u][2] = pk2(xv.z); xp[u][3] = pk2(xv.w);
            }
#pragma unroll
            for (int j = 0; j < 2; j++) {
                const int nn = 2 * c2 + 32 * j;
#pragma unroll
                for (int kk = 0; kk < 4; kk++) {
                    unsigned long long wv = d2l(*(const double*)&sw[(k + kk) * 68 + nn]);
#pragma unroll
                    for (int u = 0; u < 4; u++)
                        acc[u][j] = ffma2(xp[u][kk], wv, acc[u][j]);
                }
            }
        }
        __syncthreads();
    }

#pragma unroll
    for (int j = 0; j < 2; j++) {
        const int nn = 2 * c2 + 32 * j;
        const float b0 = bptr[ng + nn];
        const float b1 = bptr[ng + nn + 1];
#pragma unroll
        for (int u = 0; u < 4; u++) {
            const int m = m0 + mq + 16 * u;
            float2 r;
            r.x = lo32(acc[u][j]) + b0;
            r.y = hi32(acc[u][j]) + b1;
            *(float2*)&g_pre[(size_t)m * H3 + n0 + nn] = r;
        }
    }
}

// =====================================================================
// Kernel 2: persistent recurrence. 128 blocks x 512 threads,
// 8 h-columns per block, weights smem-resident, cp.async double-buffered
// h staging.  Thread = (c = tid&7 column, b = tid>>3 batch row).
// =====================================================================
extern __shared__ float smem_dyn[];

__global__ __launch_bounds__(512) void recur_kernel(
    const float* __restrict__ h0,
    const float* __restrict__ wz, const float* __restrict__ wr,
    const float* __restrict__ wh,
    float* __restrict__ out)
{
    float* sw = smem_dyn;                 // [24][SWS]
    float* sh = smem_dyn + 24 * SWS;      // [2][64][SHS]

    const int tid = threadIdx.x;
    const int j0  = blockIdx.x * 8;
    const int c   = tid & 7;
    const int b   = tid >> 3;             // 0..63

    // ---- one-time: load this block's 24 weight columns, transposed ----
    for (int idx = tid; idx < 3 * 1024 * 2; idx += 512) {
        const int g    = idx / 2048;
        const int rem  = idx - g * 2048;
        const int k    = rem >> 1;
        const int half = rem & 1;
        const float* wg = (g == 0) ? wz : (g == 1) ? wr : wh;
        float4 v = *(const float4*)(wg + (size_t)k * HID + j0 + 4 * half);
        float* dst = &sw[(g * 8 + 4 * half) * SWS + k];
        dst[0 * SWS] = v.x; dst[1 * SWS] = v.y;
        dst[2 * SWS] = v.z; dst[3 * SWS] = v.w;
    }
    __syncthreads();

    for (int t = 0; t < TT; t++) {
        const float* hprev = (t == 0) ? h0 : (out + (size_t)(t - 1) * HID);
        const long   hstr  = (t == 0) ? (long)HID : (long)TT * HID;

        // ================= phase A: z, r gates =================
        unsigned long long accZ = 0ull, accR = 0ull;

        stage_tile(sh, hprev, hstr, tid);
        for (int ch = 0; ch < NCH; ch++) {
            if (ch + 1 < NCH) {
                stage_tile(sh + ((ch + 1) & 1) * 64 * SHS,
                           hprev + (ch + 1) * CHK, hstr, tid);
                cpwait<1>();
            } else {
                cpwait<0>();
            }
            __syncthreads();

            const float* B  = sh + (ch & 1) * 64 * SHS + b * SHS;
            const int    kb = ch * CHK;
#pragma unroll
            for (int kk = 0; kk < CHK; kk += 4) {
                double2 hv  = *(const double2*)&B[kk];
                double2 wzv = *(const double2*)&sw[c * SWS + kb + kk];
                double2 wrv = *(const double2*)&sw[(8 + c) * SWS + kb + kk];
                accZ = ffma2(d2l(hv.x), d2l(wzv.x), accZ);
                accZ = ffma2(d2l(hv.y), d2l(wzv.y), accZ);
                accR = ffma2(d2l(hv.x), d2l(wrv.x), accR);
                accR = ffma2(d2l(hv.y), d2l(wrv.y), accR);
            }
            __syncthreads();
        }

        const float sz = lo32(accZ) + hi32(accZ);
        const float sr = lo32(accR) + hi32(accR);

        const float* p = g_pre + (size_t)(b * TT + t) * H3 + j0 + c;
        const float xz = __ldg(p);
        const float xr = __ldg(p + 1024);

        const float z  = sigmoidf_(sz + xz);
        const float r  = sigmoidf_(sr + xr);
        const float hp = __ldcg(hprev + (size_t)b * hstr + j0 + c);

        g_rh[(size_t)b * HID + j0 + c] = r * hp;

        gsync();   // rh complete

        // ================= phase B: hbar + update =================
        unsigned long long accH = 0ull;

        stage_tile(sh, g_rh, HID, tid);
        for (int ch = 0; ch < NCH; ch++) {
            if (ch + 1 < NCH) {
                stage_tile(sh + ((ch + 1) & 1) * 64 * SHS,
                           g_rh + (ch + 1) * CHK, HID, tid);
                cpwait<1>();
            } else {
                cpwait<0>();
            }
            __syncthreads();

            const float* B  = sh + (ch & 1) * 64 * SHS + b * SHS;
            const int    kb = ch * CHK;
#pragma unroll
            for (int kk = 0; kk < CHK; kk += 4) {
                double2 hv = *(const double2*)&B[kk];
                double2 wv = *(const double2*)&sw[(16 + c) * SWS + kb + kk];
                accH = ffma2(d2l(hv.x), d2l(wv.x), accH);
                accH = ffma2(d2l(hv.y), d2l(wv.y), accH);
            }
            __syncthreads();
        }

        const float sg = lo32(accH) + hi32(accH);
        const float xh = __ldg(g_pre + (size_t)(b * TT + t) * H3 + 2048 + j0 + c);

        const float hb = tanhf(sg + xh);
        const float hn = (1.0f - z) * hp + z * hb;

        out[((size_t)b * TT + t) * HID + j0 + c] = hn;
        if (t == TT - 1)
            out[(size_t)BSZ * TT * HID + (size_t)b * HID + j0 + c] = hn;

        gsync();   // out[:,t,:] complete before next step reads it
    }
}

// =====================================================================
extern "C" void kernel_launch(void* const* d_in, const int* in_sizes, int n_in,
                              void* d_out, int out_size)
{
    const float* x  = (const float*)d_in[0];
    const float* h0 = (const float*)d_in[1];
    const float* wz = (const float*)d_in[2];
    const float* wr = (const float*)d_in[3];
    const float* wh = (const float*)d_in[4];
    const float* bz = (const float*)d_in[5];
    const float* br = (const float*)d_in[6];
    const float* bh = (const float*)d_in[7];
    float* out = (float*)d_out;

    dim3 g1(H3 / 64, (BSZ * TT) / 64);
    xproj_kernel<<<g1, 256>>>(x, wz, wr, wh, bz, br, bh);

    const int smem_bytes = (24 * SWS + 2 * 64 * SHS) * sizeof(float);
    static bool attr_set = false;
    if (!attr_set) {
        cudaFuncSetAttribute(recur_kernel,
                             cudaFuncAttributeMaxDynamicSharedMemorySize,
                             smem_bytes);
        attr_set = true;
    }
    recur_kernel<<<NBLK, 512, smem_bytes>>>(h0, wz, wr, wh, out);
}

// round 5
// speedup vs baseline: 1.0332x; 1.0332x over previous
#include <cuda_runtime.h>
#include <cstdint>
#include <cstddef>

#define BSZ  64
#define TT   512
#define FEAT 1024
#define HID  1024
#define H3   3072
#define NBLK 128
#define SWS  1028   // smem weight row stride (floats)
#define SHS  132    // smem h row stride (floats)
#define CHK  128    // k-chunk size
#define NCH  (HID / CHK)

// Scratch for x-projections: pre[m][n], m = b*T + t, n = gate*1024 + j
__device__ float g_pre[(size_t)BSZ * TT * H3];
// Per-step scratch: (r .* h) for the hbar matmul
__device__ float g_rh[(size_t)BSZ * HID];

// grid barrier state
__device__ unsigned g_count = 0;
__device__ unsigned g_gen   = 0;

// ---------- Blackwell packed f32x2 helpers ----------
__device__ __forceinline__ unsigned long long ffma2(unsigned long long a,
                                                    unsigned long long b,
                                                    unsigned long long c) {
    unsigned long long d;
    asm("fma.rn.f32x2 %0, %1, %2, %3;" : "=l"(d) : "l"(a), "l"(b), "l"(c));
    return d;
}
__device__ __forceinline__ unsigned long long pk2(float x) {
    unsigned long long r;
    asm("mov.b64 %0, {%1, %1};" : "=l"(r) : "f"(x));
    return r;
}
__device__ __forceinline__ float lo32(unsigned long long v) {
    return __uint_as_float((unsigned)(v & 0xffffffffull));
}
__device__ __forceinline__ float hi32(unsigned long long v) {
    return __uint_as_float((unsigned)(v >> 32));
}
__device__ __forceinline__ unsigned long long d2l(double d) {
    return __double_as_longlong(d);
}
__device__ __forceinline__ float sigmoidf_(float v) {
    return 1.0f / (1.0f + expf(-v));
}

// ---------- acquire/release global ops ----------
__device__ __forceinline__ unsigned ld_acq(const unsigned* p) {
    unsigned v;
    asm volatile("ld.acquire.gpu.global.u32 %0, [%1];" : "=r"(v) : "l"(p));
    return v;
}
__device__ __forceinline__ void st_rel(unsigned* p, unsigned v) {
    asm volatile("st.release.gpu.global.u32 [%0], %1;" :: "l"(p), "r"(v));
}

// ---------- cp.async helpers ----------
__device__ __forceinline__ void cpasync16(uint32_t saddr, const void* gaddr) {
    asm volatile("cp.async.cg.shared.global [%0], [%1], 16;"
                 :: "r"(saddr), "l"(gaddr));
}
__device__ __forceinline__ void cpcommit() {
    asm volatile("cp.async.commit_group;");
}
template <int N> __device__ __forceinline__ void cpwait() {
    asm volatile("cp.async.wait_group %0;" :: "n"(N));
}

// fast software grid sync (sense-reversing, tight acquire spin)
__device__ __forceinline__ void gsync() {
    __syncthreads();
    if (threadIdx.x == 0) {
        __threadfence();                       // publish my block's stores
        const unsigned my = ld_acq(&g_gen);
        if (atomicAdd(&g_count, 1) == NBLK - 1) {
            g_count = 0;                       // ordered by release below
            st_rel(&g_gen, my + 1);
        } else {
            while (ld_acq(&g_gen) == my) { }   // ~260cyc/poll, no sleep
        }
    }
    __syncthreads();
}

// stage a 64 x CHK float tile into smem (async)
__device__ __forceinline__ void stage_tile(float* dst, const float* src,
                                           long rstride, int tid) {
#pragma unroll
    for (int i = 0; i < (64 * CHK / 4) / 512; i++) {
        int idx = tid + i * 512;
        int row = idx >> 5;          // 0..63
        int kq  = idx & 31;          // float4 index within 128-float row
        uint32_t sa = (uint32_t)__cvta_generic_to_shared(dst + row * SHS + 4 * kq);
        cpasync16(sa, src + (size_t)row * rstride + 4 * kq);
    }
    cpcommit();
}

// =====================================================================
// Kernel 1: x projections.  pre[m, n] = x[m,:] @ Wg_x[:, n%1024] + bias
// =====================================================================
__global__ __launch_bounds__(256) void xproj_kernel(
    const float* __restrict__ x,
    const float* __restrict__ wz, const float* __restrict__ wr,
    const float* __restrict__ wh,
    const float* __restrict__ bz, const float* __restrict__ br,
    const float* __restrict__ bh)
{
    __shared__ float sx[64 * 68];   // [row][k]
    __shared__ float sw[32 * 68];   // [k][n]

    const int tid = threadIdx.x;
    const int n0  = blockIdx.x * 64;
    const int m0  = blockIdx.y * 64;

    const int gate = n0 >> 10;
    const int ng   = n0 & 1023;
    const float* wptr = (gate == 0) ? wz : (gate == 1) ? wr : wh;
    const float* bptr = (gate == 0) ? bz : (gate == 1) ? br : bh;

    const int c2 = tid & 15;
    const int mq = tid >> 4;

    unsigned long long acc[4][2];
#pragma unroll
    for (int u = 0; u < 4; u++) { acc[u][0] = 0ull; acc[u][1] = 0ull; }

    const int xs_kq  = tid & 7;
    const int xs_row = tid >> 3;
    const int ws_nq  = tid & 15;
    const int ws_kr  = tid >> 4;

    for (int k0 = 0; k0 < FEAT; k0 += 32) {
#pragma unroll
        for (int i = 0; i < 2; i++) {
            int row = xs_row + 32 * i;
            float4 v = *(const float4*)(x + (size_t)(m0 + row) * FEAT + k0 + 4 * xs_kq);
            *(float4*)&sx[row * 68 + 4 * xs_kq] = v;
        }
#pragma unroll
        for (int i = 0; i < 2; i++) {
            int kr = ws_kr + 16 * i;
            float4 v = *(const float4*)(wptr + (size_t)(1024 + k0 + kr) * HID + ng + 4 * ws_nq);
            *(float4*)&sw[kr * 68 + 4 * ws_nq] = v;
        }
        __syncthreads();

#pragma unroll
        for (int k = 0; k < 32; k += 4) {
            unsigned long long xp[4][4];
#pragma unroll
            for (int u = 0; u < 4; u++) {
                float4 xv = *(const float4*)&sx[(mq + 16 * u) * 68 + k];
                xp[u][0] = pk2(xv.x); xp[u][1] = pk2(xv.y);
                xp[u][2] = pk2(xv.z); xp[u][3] = pk2(xv.w);
            }
#pragma unroll
            for (int j = 0; j < 2; j++) {
                const int nn = 2 * c2 + 32 * j;
#pragma unroll
                for (int kk = 0; kk < 4; kk++) {
                    unsigned long long wv = d2l(*(const double*)&sw[(k + kk) * 68 + nn]);
#pragma unroll
                    for (int u = 0; u < 4; u++)
                        acc[u][j] = ffma2(xp[u][kk], wv, acc[u][j]);
                }
            }
        }
        __syncthreads();
    }

#pragma unroll
    for (int j = 0; j < 2; j++) {
        const int nn = 2 * c2 + 32 * j;
        const float b0 = bptr[ng + nn];
        const float b1 = bptr[ng + nn + 1];
#pragma unroll
        for (int u = 0; u < 4; u++) {
            const int m = m0 + mq + 16 * u;
            float2 r;
            r.x = lo32(acc[u][j]) + b0;
            r.y = hi32(acc[u][j]) + b1;
            *(float2*)&g_pre[(size_t)m * H3 + n0 + nn] = r;
        }
    }
}

// =====================================================================
// Kernel 2: persistent recurrence. 128 blocks x 512 threads,
// 8 h-columns per block, weights smem-resident, cp.async double-buffered
// h staging.  Thread = (c = tid&7 column, b = tid>>3 batch row).
// =====================================================================
extern __shared__ float smem_dyn[];

__global__ __launch_bounds__(512) void recur_kernel(
    const float* __restrict__ h0,
    const float* __restrict__ wz, const float* __restrict__ wr,
    const float* __restrict__ wh,
    float* __restrict__ out)
{
    float* sw = smem_dyn;                 // [24][SWS]
    float* sh = smem_dyn + 24 * SWS;      // [2][64][SHS]

    const int tid = threadIdx.x;
    const int j0  = blockIdx.x * 8;
    const int c   = tid & 7;
    const int b   = tid >> 3;             // 0..63

    // ---- one-time: load this block's 24 weight columns, transposed ----
    for (int idx = tid; idx < 3 * 1024 * 2; idx += 512) {
        const int g    = idx / 2048;
        const int rem  = idx - g * 2048;
        const int k    = rem >> 1;
        const int half = rem & 1;
        const float* wg = (g == 0) ? wz : (g == 1) ? wr : wh;
        float4 v = *(const float4*)(wg + (size_t)k * HID + j0 + 4 * half);
        float* dst = &sw[(g * 8 + 4 * half) * SWS + k];
        dst[0 * SWS] = v.x; dst[1 * SWS] = v.y;
        dst[2 * SWS] = v.z; dst[3 * SWS] = v.w;
    }
    __syncthreads();

    for (int t = 0; t < TT; t++) {
        const float* hprev = (t == 0) ? h0 : (out + (size_t)(t - 1) * HID);
        const long   hstr  = (t == 0) ? (long)HID : (long)TT * HID;

        // ================= phase A: z, r gates =================
        unsigned long long accZ = 0ull, accR = 0ull;

        // prefetch this step's pointwise operands early (hide L2/DRAM)
        const float* p  = g_pre + (size_t)(b * TT + t) * H3 + j0 + c;
        const float xz  = __ldg(p);
        const float xr  = __ldg(p + 1024);
        const float xh  = __ldg(p + 2048);
        const float hp  = __ldcg(hprev + (size_t)b * hstr + j0 + c);

        stage_tile(sh, hprev, hstr, tid);
        for (int ch = 0; ch < NCH; ch++) {
            if (ch + 1 < NCH) {
                stage_tile(sh + ((ch + 1) & 1) * 64 * SHS,
                           hprev + (ch + 1) * CHK, hstr, tid);
                cpwait<1>();
            } else {
                cpwait<0>();
            }
            __syncthreads();

            const float* B  = sh + (ch & 1) * 64 * SHS + b * SHS;
            const int    kb = ch * CHK;
#pragma unroll
            for (int kk = 0; kk < CHK; kk += 4) {
                double2 hv  = *(const double2*)&B[kk];
                double2 wzv = *(const double2*)&sw[c * SWS + kb + kk];
                double2 wrv = *(const double2*)&sw[(8 + c) * SWS + kb + kk];
                accZ = ffma2(d2l(hv.x), d2l(wzv.x), accZ);
                accZ = ffma2(d2l(hv.y), d2l(wzv.y), accZ);
                accR = ffma2(d2l(hv.x), d2l(wrv.x), accR);
                accR = ffma2(d2l(hv.y), d2l(wrv.y), accR);
            }
            __syncthreads();
        }

        const float sz = lo32(accZ) + hi32(accZ);
        const float sr = lo32(accR) + hi32(accR);

        const float z  = sigmoidf_(sz + xz);
        const float r  = sigmoidf_(sr + xr);

        g_rh[(size_t)b * HID + j0 + c] = r * hp;

        gsync();   // rh complete

        // ================= phase B: hbar + update =================
        unsigned long long accH = 0ull;

        stage_tile(sh, g_rh, HID, tid);
        for (int ch = 0; ch < NCH; ch++) {
            if (ch + 1 < NCH) {
                stage_tile(sh + ((ch + 1) & 1) * 64 * SHS,
                           g_rh + (ch + 1) * CHK, HID, tid);
                cpwait<1>();
            } else {
                cpwait<0>();
            }
            __syncthreads();

            const float* B  = sh + (ch & 1) * 64 * SHS + b * SHS;
            const int    kb = ch * CHK;
#pragma unroll
            for (int kk = 0; kk < CHK; kk += 4) {
                double2 hv = *(const double2*)&B[kk];
                double2 wv = *(const double2*)&sw[(16 + c) * SWS + kb + kk];
                accH = ffma2(d2l(hv.x), d2l(wv.x), accH);
                accH = ffma2(d2l(hv.y), d2l(wv.y), accH);
            }
            __syncthreads();
        }

        const float sg = lo32(accH) + hi32(accH);

        const float hb = tanhf(sg + xh);
        const float hn = (1.0f - z) * hp + z * hb;

        out[((size_t)b * TT + t) * HID + j0 + c] = hn;
        if (t == TT - 1)
            out[(size_t)BSZ * TT * HID + (size_t)b * HID + j0 + c] = hn;

        gsync();   // out[:,t,:] complete before next step reads it
    }
}

// =====================================================================
extern "C" void kernel_launch(void* const* d_in, const int* in_sizes, int n_in,
                              void* d_out, int out_size)
{
    const float* x  = (const float*)d_in[0];
    const float* h0 = (const float*)d_in[1];
    const float* wz = (const float*)d_in[2];
    const float* wr = (const float*)d_in[3];
    const float* wh = (const float*)d_in[4];
    const float* bz = (const float*)d_in[5];
    const float* br = (const float*)d_in[6];
    const float* bh = (const float*)d_in[7];
    float* out = (float*)d_out;

    dim3 g1(H3 / 64, (BSZ * TT) / 64);
    xproj_kernel<<<g1, 256>>>(x, wz, wr, wh, bz, br, bh);

    const int smem_bytes = (24 * SWS + 2 * 64 * SHS) * sizeof(float);
    static bool attr_set = false;
    if (!attr_set) {
        cudaFuncSetAttribute(recur_kernel,
                             cudaFuncAttributeMaxDynamicSharedMemorySize,
                             smem_bytes);
        attr_set = true;
    }
    recur_kernel<<<NBLK, 512, smem_bytes>>>(h0, wz, wr, wh, out);
}

// round 6
// speedup vs baseline: 1.0396x; 1.0062x over previous
#include <cuda_runtime.h>
#include <cstdint>
#include <cstddef>

#define BSZ  64
#define TT   512
#define FEAT 1024
#define HID  1024
#define H3   3072
#define NBLK 128
#define SWS  1028   // recur smem weight row stride (floats)
#define SHS  132    // recur smem h row stride (floats)
#define CHK  128    // recur k-chunk size
#define NCH  (HID / CHK)

#define XCHK 64     // xproj k-chunk
#define XS   68     // xproj smem row stride

// Scratch for x-projections: pre[m][n], m = b*T + t, n = gate*1024 + j
__device__ float g_pre[(size_t)BSZ * TT * H3];
// Per-step scratch: (r .* h) for the hbar matmul
__device__ float g_rh[(size_t)BSZ * HID];

// grid barrier state
__device__ unsigned g_count = 0;
__device__ unsigned g_gen   = 0;

// ---------- Blackwell packed f32x2 helpers ----------
__device__ __forceinline__ unsigned long long ffma2(unsigned long long a,
                                                    unsigned long long b,
                                                    unsigned long long c) {
    unsigned long long d;
    asm("fma.rn.f32x2 %0, %1, %2, %3;" : "=l"(d) : "l"(a), "l"(b), "l"(c));
    return d;
}
__device__ __forceinline__ unsigned long long pk2(float x) {
    unsigned long long r;
    asm("mov.b64 %0, {%1, %1};" : "=l"(r) : "f"(x));
    return r;
}
__device__ __forceinline__ float lo32(unsigned long long v) {
    return __uint_as_float((unsigned)(v & 0xffffffffull));
}
__device__ __forceinline__ float hi32(unsigned long long v) {
    return __uint_as_float((unsigned)(v >> 32));
}
__device__ __forceinline__ unsigned long long d2l(double d) {
    return __double_as_longlong(d);
}
__device__ __forceinline__ float sigmoidf_(float v) {
    return 1.0f / (1.0f + expf(-v));
}

// ---------- acquire/release global ops ----------
__device__ __forceinline__ unsigned ld_acq(const unsigned* p) {
    unsigned v;
    asm volatile("ld.acquire.gpu.global.u32 %0, [%1];" : "=r"(v) : "l"(p));
    return v;
}
__device__ __forceinline__ void st_rel(unsigned* p, unsigned v) {
    asm volatile("st.release.gpu.global.u32 [%0], %1;" :: "l"(p), "r"(v));
}

// ---------- cp.async helpers ----------
__device__ __forceinline__ void cpasync16(uint32_t saddr, const void* gaddr) {
    asm volatile("cp.async.cg.shared.global [%0], [%1], 16;"
                 :: "r"(saddr), "l"(gaddr));
}
__device__ __forceinline__ void cpcommit() {
    asm volatile("cp.async.commit_group;");
}
template <int N> __device__ __forceinline__ void cpwait() {
    asm volatile("cp.async.wait_group %0;" :: "n"(N));
}

// fast software grid sync (sense-reversing, tight acquire spin)
__device__ __forceinline__ void gsync() {
    __syncthreads();
    if (threadIdx.x == 0) {
        __threadfence();
        const unsigned my = ld_acq(&g_gen);
        if (atomicAdd(&g_count, 1) == NBLK - 1) {
            g_count = 0;
            st_rel(&g_gen, my + 1);
        } else {
            while (ld_acq(&g_gen) == my) { }
        }
    }
    __syncthreads();
}

extern __shared__ float smem_dyn[];

// =====================================================================
// Kernel 1: x projections.  pre[m, n] = x[m,:] @ Wg_x[:, n%1024] + bias
// Tile 64m x 64n, k chunks of 64, cp.async double-buffered.
// Split into 3 launches over m (also lets ncu -s5 land on this kernel).
// =====================================================================
__global__ __launch_bounds__(256) void xproj_kernel(
    const float* __restrict__ x,
    const float* __restrict__ wz, const float* __restrict__ wr,
    const float* __restrict__ wh,
    const float* __restrict__ bz, const float* __restrict__ br,
    const float* __restrict__ bh, int m_off)
{
    float* sx = smem_dyn;                  // [2][64][XS]
    float* swt = smem_dyn + 2 * 64 * XS;   // [2][64][XS]

    const int tid = threadIdx.x;
    const int n0  = blockIdx.x * 64;
    const int m0  = (m_off + blockIdx.y) * 64;

    const int gate = n0 >> 10;
    const int ng   = n0 & 1023;
    const float* wptr = (gate == 0) ? wz : (gate == 1) ? wr : wh;
    const float* bptr = (gate == 0) ? bz : (gate == 1) ? br : bh;

    const int c2 = tid & 15;   // n-pair id
    const int mq = tid >> 4;   // 0..15

    unsigned long long acc[4][2];
#pragma unroll
    for (int u = 0; u < 4; u++) { acc[u][0] = 0ull; acc[u][1] = 0ull; }

    const int s_row = tid >> 4;       // 0..15 (x rows / w k-rows, 4 iters)
    const int s_q   = tid & 15;       // float4 index within 64-float row

    // stage chunk k0 into buffer buf
    auto stage = [&](int buf, int k0) {
#pragma unroll
        for (int i = 0; i < 4; i++) {
            int row = s_row + 16 * i;
            uint32_t sa = (uint32_t)__cvta_generic_to_shared(
                sx + buf * 64 * XS + row * XS + 4 * s_q);
            cpasync16(sa, x + (size_t)(m0 + row) * FEAT + k0 + 4 * s_q);
        }
#pragma unroll
        for (int i = 0; i < 4; i++) {
            int kr = s_row + 16 * i;
            uint32_t sa = (uint32_t)__cvta_generic_to_shared(
                swt + buf * 64 * XS + kr * XS + 4 * s_q);
            cpasync16(sa, wptr + (size_t)(1024 + k0 + kr) * HID + ng + 4 * s_q);
        }
        cpcommit();
    };

    stage(0, 0);
    for (int ch = 0; ch < FEAT / XCHK; ch++) {
        if (ch + 1 < FEAT / XCHK) {
            stage((ch + 1) & 1, (ch + 1) * XCHK);
            cpwait<1>();
        } else {
            cpwait<0>();
        }
        __syncthreads();

        const float* SX = sx  + (ch & 1) * 64 * XS;
        const float* SW = swt + (ch & 1) * 64 * XS;

#pragma unroll
        for (int k = 0; k < XCHK; k += 4) {
            unsigned long long xp[4][4];
#pragma unroll
            for (int u = 0; u < 4; u++) {
                float4 xv = *(const float4*)&SX[(mq + 16 * u) * XS + k];
                xp[u][0] = pk2(xv.x); xp[u][1] = pk2(xv.y);
                xp[u][2] = pk2(xv.z); xp[u][3] = pk2(xv.w);
            }
#pragma unroll
            for (int j = 0; j < 2; j++) {
                const int nn = 2 * c2 + 32 * j;
#pragma unroll
                for (int kk = 0; kk < 4; kk++) {
                    unsigned long long wv = d2l(*(const double*)&SW[(k + kk) * XS + nn]);
#pragma unroll
                    for (int u = 0; u < 4; u++)
                        acc[u][j] = ffma2(xp[u][kk], wv, acc[u][j]);
                }
            }
        }
        __syncthreads();
    }

#pragma unroll
    for (int j = 0; j < 2; j++) {
        const int nn = 2 * c2 + 32 * j;
        const float b0 = bptr[ng + nn];
        const float b1 = bptr[ng + nn + 1];
#pragma unroll
        for (int u = 0; u < 4; u++) {
            const int m = m0 + mq + 16 * u;
            float2 r;
            r.x = lo32(acc[u][j]) + b0;
            r.y = hi32(acc[u][j]) + b1;
            *(float2*)&g_pre[(size_t)m * H3 + n0 + nn] = r;
        }
    }
}

// =====================================================================
// Kernel 2: persistent recurrence (unchanged from R5).
// =====================================================================
__global__ __launch_bounds__(512) void recur_kernel(
    const float* __restrict__ h0,
    const float* __restrict__ wz, const float* __restrict__ wr,
    const float* __restrict__ wh,
    float* __restrict__ out)
{
    float* sw = smem_dyn;                 // [24][SWS]
    float* sh = smem_dyn + 24 * SWS;      // [2][64][SHS]

    const int tid = threadIdx.x;
    const int j0  = blockIdx.x * 8;
    const int c   = tid & 7;
    const int b   = tid >> 3;             // 0..63

    for (int idx = tid; idx < 3 * 1024 * 2; idx += 512) {
        const int g    = idx / 2048;
        const int rem  = idx - g * 2048;
        const int k    = rem >> 1;
        const int half = rem & 1;
        const float* wg = (g == 0) ? wz : (g == 1) ? wr : wh;
        float4 v = *(const float4*)(wg + (size_t)k * HID + j0 + 4 * half);
        float* dst = &sw[(g * 8 + 4 * half) * SWS + k];
        dst[0 * SWS] = v.x; dst[1 * SWS] = v.y;
        dst[2 * SWS] = v.z; dst[3 * SWS] = v.w;
    }
    __syncthreads();

    const int st_row = tid >> 5;          // staging: not used directly

    for (int t = 0; t < TT; t++) {
        const float* hprev = (t == 0) ? h0 : (out + (size_t)(t - 1) * HID);
        const long   hstr  = (t == 0) ? (long)HID : (long)TT * HID;

        // ================= phase A: z, r gates =================
        unsigned long long accZ = 0ull, accR = 0ull;

        const float* p  = g_pre + (size_t)(b * TT + t) * H3 + j0 + c;
        const float xz  = __ldg(p);
        const float xr  = __ldg(p + 1024);
        const float xh  = __ldg(p + 2048);
        const float hp  = __ldcg(hprev + (size_t)b * hstr + j0 + c);

        // stage helper inline (64 x CHK tile)
        auto stageh = [&](float* dst, const float* src, long rstride) {
#pragma unroll
            for (int i = 0; i < (64 * CHK / 4) / 512; i++) {
                int idx = tid + i * 512;
                int row = idx >> 5;
                int kq  = idx & 31;
                uint32_t sa = (uint32_t)__cvta_generic_to_shared(dst + row * SHS + 4 * kq);
                cpasync16(sa, src + (size_t)row * rstride + 4 * kq);
            }
            cpcommit();
        };

        stageh(sh, hprev, hstr);
        for (int ch = 0; ch < NCH; ch++) {
            if (ch + 1 < NCH) {
                stageh(sh + ((ch + 1) & 1) * 64 * SHS, hprev + (ch + 1) * CHK, hstr);
                cpwait<1>();
            } else {
                cpwait<0>();
            }
            __syncthreads();

            const float* B  = sh + (ch & 1) * 64 * SHS + b * SHS;
            const int    kb = ch * CHK;
#pragma unroll
            for (int kk = 0; kk < CHK; kk += 4) {
                double2 hv  = *(const double2*)&B[kk];
                double2 wzv = *(const double2*)&sw[c * SWS + kb + kk];
                double2 wrv = *(const double2*)&sw[(8 + c) * SWS + kb + kk];
                accZ = ffma2(d2l(hv.x), d2l(wzv.x), accZ);
                accZ = ffma2(d2l(hv.y), d2l(wzv.y), accZ);
                accR = ffma2(d2l(hv.x), d2l(wrv.x), accR);
                accR = ffma2(d2l(hv.y), d2l(wrv.y), accR);
            }
            __syncthreads();
        }

        const float sz = lo32(accZ) + hi32(accZ);
        const float sr = lo32(accR) + hi32(accR);

        const float z  = sigmoidf_(sz + xz);
        const float r  = sigmoidf_(sr + xr);

        g_rh[(size_t)b * HID + j0 + c] = r * hp;

        gsync();   // rh complete

        // ================= phase B: hbar + update =================
        unsigned long long accH = 0ull;

        stageh(sh, g_rh, HID);
        for (int ch = 0; ch < NCH; ch++) {
            if (ch + 1 < NCH) {
                stageh(sh + ((ch + 1) & 1) * 64 * SHS, g_rh + (ch + 1) * CHK, HID);
                cpwait<1>();
            } else {
                cpwait<0>();
            }
            __syncthreads();

            const float* B  = sh + (ch & 1) * 64 * SHS + b * SHS;
            const int    kb = ch * CHK;
#pragma unroll
            for (int kk = 0; kk < CHK; kk += 4) {
                double2 hv = *(const double2*)&B[kk];
                double2 wv = *(const double2*)&sw[(16 + c) * SWS + kb + kk];
                accH = ffma2(d2l(hv.x), d2l(wv.x), accH);
                accH = ffma2(d2l(hv.y), d2l(wv.y), accH);
            }
            __syncthreads();
        }

        const float sg = lo32(accH) + hi32(accH);

        const float hb = tanhf(sg + xh);
        const float hn = (1.0f - z) * hp + z * hb;

        out[((size_t)b * TT + t) * HID + j0 + c] = hn;
        if (t == TT - 1)
            out[(size_t)BSZ * TT * HID + (size_t)b * HID + j0 + c] = hn;

        gsync();   // out[:,t,:] complete before next step reads it
    }
}

// =====================================================================
extern "C" void kernel_launch(void* const* d_in, const int* in_sizes, int n_in,
                              void* d_out, int out_size)
{
    const float* x  = (const float*)d_in[0];
    const float* h0 = (const float*)d_in[1];
    const float* wz = (const float*)d_in[2];
    const float* wr = (const float*)d_in[3];
    const float* wh = (const float*)d_in[4];
    const float* bz = (const float*)d_in[5];
    const float* br = (const float*)d_in[6];
    const float* bh = (const float*)d_in[7];
    float* out = (float*)d_out;

    const int x_smem = 4 * 64 * XS * sizeof(float);          // 69.6 KB
    const int r_smem = (24 * SWS + 2 * 64 * SHS) * sizeof(float);
    static bool attr_set = false;
    if (!attr_set) {
        cudaFuncSetAttribute(xproj_kernel,
                             cudaFuncAttributeMaxDynamicSharedMemorySize, x_smem);
        cudaFuncSetAttribute(recur_kernel,
                             cudaFuncAttributeMaxDynamicSharedMemorySize, r_smem);
        attr_set = true;
    }

    // 3 m-splits of 512 row-blocks: 171 + 171 + 170
    const int ysplit[4] = {0, 171, 342, 512};
    for (int s = 0; s < 3; s++) {
        dim3 g1(H3 / 64, ysplit[s + 1] - ysplit[s]);
        xproj_kernel<<<g1, 256, x_smem>>>(x, wz, wr, wh, bz, br, bh, ysplit[s]);
    }

    recur_kernel<<<NBLK, 512, r_smem>>>(h0, wz, wr, wh, out);
}

// round 7
// speedup vs baseline: 1.1493x; 1.1055x over previous
#include <cuda_runtime.h>
#include <cstdint>
#include <cstddef>

#define BSZ  64
#define TT   512
#define FEAT 1024
#define HID  1024
#define H3   3072
#define NBLK 128
#define SWS  1028   // recur smem weight row stride (floats)
#define SHS  132    // recur smem h row stride (floats)
#define CHK  128    // recur k-chunk size
#define NCH  (HID / CHK)

#define XCHK 64     // xproj k-chunk
#define XS   68     // xproj smem row stride

// Scratch for x-projections: pre[m][n], m = b*T + t, n = gate*1024 + j
__device__ float g_pre[(size_t)BSZ * TT * H3];
// Per-step scratch: (r .* h) for the hbar matmul
__device__ float g_rh[(size_t)BSZ * HID];

// grid barrier state — separate 128B lines (atomic vs spin-load isolation)
__device__ __align__(128) unsigned g_count_arr[32];
__device__ __align__(128) unsigned g_gen_arr[32];

// ---------- Blackwell packed f32x2 helpers ----------
__device__ __forceinline__ unsigned long long ffma2(unsigned long long a,
                                                    unsigned long long b,
                                                    unsigned long long c) {
    unsigned long long d;
    asm("fma.rn.f32x2 %0, %1, %2, %3;" : "=l"(d) : "l"(a), "l"(b), "l"(c));
    return d;
}
__device__ __forceinline__ float lo32(unsigned long long v) {
    return __uint_as_float((unsigned)(v & 0xffffffffull));
}
__device__ __forceinline__ float hi32(unsigned long long v) {
    return __uint_as_float((unsigned)(v >> 32));
}
__device__ __forceinline__ unsigned long long d2l(double d) {
    return __double_as_longlong(d);
}
__device__ __forceinline__ float sigmoidf_(float v) {
    return 1.0f / (1.0f + expf(-v));
}

// ---------- tf32 mma helpers ----------
__device__ __forceinline__ uint32_t cvt_tf32(float x) {
    uint32_t r;
    asm("cvt.rna.tf32.f32 %0, %1;" : "=r"(r) : "f"(x));
    return r;
}
__device__ __forceinline__ void mma_tf32(float* c, const uint32_t* a,
                                         const uint32_t* b) {
    asm volatile(
        "mma.sync.aligned.m16n8k8.row.col.f32.tf32.tf32.f32 "
        "{%0,%1,%2,%3}, {%4,%5,%6,%7}, {%8,%9}, {%0,%1,%2,%3};"
        : "+f"(c[0]), "+f"(c[1]), "+f"(c[2]), "+f"(c[3])
        : "r"(a[0]), "r"(a[1]), "r"(a[2]), "r"(a[3]),
          "r"(b[0]), "r"(b[1]));
}

// ---------- acquire/release global ops ----------
__device__ __forceinline__ unsigned ld_acq(const unsigned* p) {
    unsigned v;
    asm volatile("ld.acquire.gpu.global.u32 %0, [%1];" : "=r"(v) : "l"(p));
    return v;
}
__device__ __forceinline__ void st_rel(unsigned* p, unsigned v) {
    asm volatile("st.release.gpu.global.u32 [%0], %1;" :: "l"(p), "r"(v));
}

// ---------- cp.async helpers ----------
__device__ __forceinline__ void cpasync16(uint32_t saddr, const void* gaddr) {
    asm volatile("cp.async.cg.shared.global [%0], [%1], 16;"
                 :: "r"(saddr), "l"(gaddr));
}
__device__ __forceinline__ void cpcommit() {
    asm volatile("cp.async.commit_group;");
}
template <int N> __device__ __forceinline__ void cpwait() {
    asm volatile("cp.async.wait_group %0;" :: "n"(N));
}

// fast software grid sync (sense-reversing, tight acquire spin)
__device__ __forceinline__ void gsync() {
    __syncthreads();
    if (threadIdx.x == 0) {
        __threadfence();
        const unsigned my = ld_acq(&g_gen_arr[0]);
        if (atomicAdd(&g_count_arr[0], 1) == NBLK - 1) {
            g_count_arr[0] = 0;
            st_rel(&g_gen_arr[0], my + 1);
        } else {
            while (ld_acq(&g_gen_arr[0]) == my) { }
        }
    }
    __syncthreads();
}

extern __shared__ float smem_dyn[];

// =====================================================================
// Kernel 1: x projections (tf32 mma.sync).
// Block: 64m x 64n, K=1024, chunks of 64 k (cp.async double-buffered).
// 8 warps = 2m x 2n x 2k-split; warp tile 32m x 32n over 512 k.
// =====================================================================
__global__ __launch_bounds__(256) void xproj_kernel(
    const float* __restrict__ x,
    const float* __restrict__ wz, const float* __restrict__ wr,
    const float* __restrict__ wh,
    const float* __restrict__ bz, const float* __restrict__ br,
    const float* __restrict__ bh, int m_off)
{
    float* sx  = smem_dyn;                 // [2][64][XS]  x tile [m][k]
    float* swt = smem_dyn + 2 * 64 * XS;   // [2][64][XS]  w tile [k][n]

    const int tid = threadIdx.x;
    const int n0  = blockIdx.x * 64;
    const int m0  = (m_off + blockIdx.y) * 64;

    const int gate = n0 >> 10;
    const int ng   = n0 & 1023;
    const float* wptr = (gate == 0) ? wz : (gate == 1) ? wr : wh;
    const float* bptr = (gate == 0) ? bz : (gate == 1) ? br : bh;

    const int w  = tid >> 5;
    const int l  = tid & 31;
    const int kw = w >> 2;          // k half (0: k 0..31 of chunk, 1: 32..63)
    const int mw = (w >> 1) & 1;    // m half
    const int nw = w & 1;           // n half

    float c[2][4][4];               // [m-tile][n-tile][reg]
#pragma unroll
    for (int mt = 0; mt < 2; mt++)
#pragma unroll
        for (int nt = 0; nt < 4; nt++)
#pragma unroll
            for (int r = 0; r < 4; r++) c[mt][nt][r] = 0.0f;

    const int s_row = tid >> 4;     // 0..15
    const int s_q   = tid & 15;     // float4 idx within 64-float row

    auto stage = [&](int buf, int k0) {
#pragma unroll
        for (int i = 0; i < 4; i++) {
            int row = s_row + 16 * i;
            uint32_t sa = (uint32_t)__cvta_generic_to_shared(
                sx + buf * 64 * XS + row * XS + 4 * s_q);
            cpasync16(sa, x + (size_t)(m0 + row) * FEAT + k0 + 4 * s_q);
        }
#pragma unroll
        for (int i = 0; i < 4; i++) {
            int kr = s_row + 16 * i;
            uint32_t sa = (uint32_t)__cvta_generic_to_shared(
                swt + buf * 64 * XS + kr * XS + 4 * s_q);
            cpasync16(sa, wptr + (size_t)(1024 + k0 + kr) * HID + ng + 4 * s_q);
        }
        cpcommit();
    };

    const int ar = l >> 2, ac = l & 3;      // A frag thread coords
    const int bk = l & 3,  bn = l >> 2;     // B frag thread coords

    stage(0, 0);
    for (int ch = 0; ch < FEAT / XCHK; ch++) {
        if (ch + 1 < FEAT / XCHK) {
            stage((ch + 1) & 1, (ch + 1) * XCHK);
            cpwait<1>();
        } else {
            cpwait<0>();
        }
        __syncthreads();

        const float* SX = sx  + (ch & 1) * 64 * XS;
        const float* SW = swt + (ch & 1) * 64 * XS;

#pragma unroll
        for (int kt = 0; kt < 4; kt++) {
            const int k = kw * 32 + kt * 8;

            uint32_t a[2][4];
#pragma unroll
            for (int mt = 0; mt < 2; mt++) {
                const float* P = SX + (mw * 32 + mt * 16 + ar) * XS + k + ac;
                a[mt][0] = cvt_tf32(P[0]);
                a[mt][1] = cvt_tf32(P[8 * XS]);
                a[mt][2] = cvt_tf32(P[4]);
                a[mt][3] = cvt_tf32(P[8 * XS + 4]);
            }
            uint32_t b[4][2];
#pragma unroll
            for (int nt = 0; nt < 4; nt++) {
                const float* Q = SW + (k + bk) * XS + nw * 32 + nt * 8 + bn;
                b[nt][0] = cvt_tf32(Q[0]);
                b[nt][1] = cvt_tf32(Q[4 * XS]);
            }
#pragma unroll
            for (int mt = 0; mt < 2; mt++)
#pragma unroll
                for (int nt = 0; nt < 4; nt++)
                    mma_tf32(c[mt][nt], a[mt], b[nt]);
        }
        __syncthreads();
    }

    // ---- k-split reduce (kw=1 -> smem -> kw=0 adds) + epilogue ----
    float* sred = smem_dyn;   // reuse staging smem: 4 tiles of 32x32
    if (kw == 1) {
        float* dst = sred + (mw * 2 + nw) * 1024;
#pragma unroll
        for (int mt = 0; mt < 2; mt++)
#pragma unroll
            for (int nt = 0; nt < 4; nt++)
#pragma unroll
                for (int r = 0; r < 4; r++) {
                    int row = mt * 16 + (l >> 2) + (r >= 2 ? 8 : 0);
                    int col = nt * 8 + 2 * (l & 3) + (r & 1);
                    dst[row * 32 + col] = c[mt][nt][r];
                }
    }
    __syncthreads();
    if (kw == 0) {
        const float* src = sred + (mw * 2 + nw) * 1024;
#pragma unroll
        for (int mt = 0; mt < 2; mt++)
#pragma unroll
            for (int nt = 0; nt < 4; nt++) {
#pragma unroll
                for (int r = 0; r < 4; r++) {
                    int row = mt * 16 + (l >> 2) + (r >= 2 ? 8 : 0);
                    int col = nt * 8 + 2 * (l & 3) + (r & 1);
                    c[mt][nt][r] += src[row * 32 + col];
                }
#pragma unroll
                for (int half = 0; half < 2; half++) {
                    const int row = mt * 16 + (l >> 2) + 8 * half;
                    const int nbase = nw * 32 + nt * 8 + 2 * (l & 3);
                    float2 v;
                    v.x = c[mt][nt][2 * half + 0] + bptr[ng + nbase];
                    v.y = c[mt][nt][2 * half + 1] + bptr[ng + nbase + 1];
                    *(float2*)&g_pre[(size_t)(m0 + mw * 32 + row) * H3 + n0 + nbase] = v;
                }
            }
    }
}

// =====================================================================
// Kernel 2: persistent recurrence (as R6; padded barrier lines).
// =====================================================================
__global__ __launch_bounds__(512) void recur_kernel(
    const float* __restrict__ h0,
    const float* __restrict__ wz, const float* __restrict__ wr,
    const float* __restrict__ wh,
    float* __restrict__ out)
{
    float* sw = smem_dyn;                 // [24][SWS]
    float* sh = smem_dyn + 24 * SWS;      // [2][64][SHS]

    const int tid = threadIdx.x;
    const int j0  = blockIdx.x * 8;
    const int c   = tid & 7;
    const int b   = tid >> 3;             // 0..63

    for (int idx = tid; idx < 3 * 1024 * 2; idx += 512) {
        const int g    = idx / 2048;
        const int rem  = idx - g * 2048;
        const int k    = rem >> 1;
        const int half = rem & 1;
        const float* wg = (g == 0) ? wz : (g == 1) ? wr : wh;
        float4 v = *(const float4*)(wg + (size_t)k * HID + j0 + 4 * half);
        float* dst = &sw[(g * 8 + 4 * half) * SWS + k];
        dst[0 * SWS] = v.x; dst[1 * SWS] = v.y;
        dst[2 * SWS] = v.z; dst[3 * SWS] = v.w;
    }
    __syncthreads();

    for (int t = 0; t < TT; t++) {
        const float* hprev = (t == 0) ? h0 : (out + (size_t)(t - 1) * HID);
        const long   hstr  = (t == 0) ? (long)HID : (long)TT * HID;

        unsigned long long accZ = 0ull, accR = 0ull;

        const float* p  = g_pre + (size_t)(b * TT + t) * H3 + j0 + c;
        const float xz  = __ldg(p);
        const float xr  = __ldg(p + 1024);
        const float xh  = __ldg(p + 2048);
        const float hp  = __ldcg(hprev + (size_t)b * hstr + j0 + c);

        auto stageh = [&](float* dst, const float* src, long rstride) {
#pragma unroll
            for (int i = 0; i < (64 * CHK / 4) / 512; i++) {
                int idx = tid + i * 512;
                int row = idx >> 5;
                int kq  = idx & 31;
                uint32_t sa = (uint32_t)__cvta_generic_to_shared(dst + row * SHS + 4 * kq);
                cpasync16(sa, src + (size_t)row * rstride + 4 * kq);
            }
            cpcommit();
        };

        stageh(sh, hprev, hstr);
        for (int ch = 0; ch < NCH; ch++) {
            if (ch + 1 < NCH) {
                stageh(sh + ((ch + 1) & 1) * 64 * SHS, hprev + (ch + 1) * CHK, hstr);
                cpwait<1>();
            } else {
                cpwait<0>();
            }
            __syncthreads();

            const float* B  = sh + (ch & 1) * 64 * SHS + b * SHS;
            const int    kb = ch * CHK;
#pragma unroll
            for (int kk = 0; kk < CHK; kk += 4) {
                double2 hv  = *(const double2*)&B[kk];
                double2 wzv = *(const double2*)&sw[c * SWS + kb + kk];
                double2 wrv = *(const double2*)&sw[(8 + c) * SWS + kb + kk];
                accZ = ffma2(d2l(hv.x), d2l(wzv.x), accZ);
                accZ = ffma2(d2l(hv.y), d2l(wzv.y), accZ);
                accR = ffma2(d2l(hv.x), d2l(wrv.x), accR);
                accR = ffma2(d2l(hv.y), d2l(wrv.y), accR);
            }
            __syncthreads();
        }

        const float sz = lo32(accZ) + hi32(accZ);
        const float sr = lo32(accR) + hi32(accR);

        const float z  = sigmoidf_(sz + xz);
        const float r  = sigmoidf_(sr + xr);

        g_rh[(size_t)b * HID + j0 + c] = r * hp;

        gsync();   // rh complete

        unsigned long long accH = 0ull;

        stageh(sh, g_rh, HID);
        for (int ch = 0; ch < NCH; ch++) {
            if (ch + 1 < NCH) {
                stageh(sh + ((ch + 1) & 1) * 64 * SHS, g_rh + (ch + 1) * CHK, HID);
                cpwait<1>();
            } else {
                cpwait<0>();
            }
            __syncthreads();

            const float* B  = sh + (ch & 1) * 64 * SHS + b * SHS;
            const int    kb = ch * CHK;
#pragma unroll
            for (int kk = 0; kk < CHK; kk += 4) {
                double2 hv = *(const double2*)&B[kk];
                double2 wv = *(const double2*)&sw[(16 + c) * SWS + kb + kk];
                accH = ffma2(d2l(hv.x), d2l(wv.x), accH);
                accH = ffma2(d2l(hv.y), d2l(wv.y), accH);
            }
            __syncthreads();
        }

        const float sg = lo32(accH) + hi32(accH);

        const float hb = tanhf(sg + xh);
        const float hn = (1.0f - z) * hp + z * hb;

        out[((size_t)b * TT + t) * HID + j0 + c] = hn;
        if (t == TT - 1)
            out[(size_t)BSZ * TT * HID + (size_t)b * HID + j0 + c] = hn;

        gsync();   // out[:,t,:] complete before next step reads it
    }
}

// =====================================================================
extern "C" void kernel_launch(void* const* d_in, const int* in_sizes, int n_in,
                              void* d_out, int out_size)
{
    const float* x  = (const float*)d_in[0];
    const float* h0 = (const float*)d_in[1];
    const float* wz = (const float*)d_in[2];
    const float* wr = (const float*)d_in[3];
    const float* wh = (const float*)d_in[4];
    const float* bz = (const float*)d_in[5];
    const float* br = (const float*)d_in[6];
    const float* bh = (const float*)d_in[7];
    float* out = (float*)d_out;

    const int x_smem = 4 * 64 * XS * sizeof(float);          // 69.6 KB
    const int r_smem = (24 * SWS + 2 * 64 * SHS) * sizeof(float);
    static bool attr_set = false;
    if (!attr_set) {
        cudaFuncSetAttribute(xproj_kernel,
                             cudaFuncAttributeMaxDynamicSharedMemorySize, x_smem);
        cudaFuncSetAttribute(recur_kernel,
                             cudaFuncAttributeMaxDynamicSharedMemorySize, r_smem);
        attr_set = true;
    }

    const int ysplit[4] = {0, 171, 342, 512};
    for (int s = 0; s < 3; s++) {
        dim3 g1(H3 / 64, ysplit[s + 1] - ysplit[s]);
        xproj_kernel<<<g1, 256, x_smem>>>(x, wz, wr, wh, bz, br, bh, ysplit[s]);
    }

    recur_kernel<<<NBLK, 512, r_smem>>>(h0, wz, wr, wh, out);
}

// round 8
// speedup vs baseline: 2.7335x; 2.3784x over previous
#include <cuda_runtime.h>
#include <cstdint>
#include <cstddef>

#define BSZ  64
#define TT   512
#define FEAT 1024
#define HID  1024
#define H3   3072
#define NBLK 128

#define XCHK 64     // xproj k-chunk
#define XS   68     // xproj smem row stride

#define AST  1028   // recur staged-A row stride (floats), conflict-free
#define MR   16     // recur m-chunk rows
#define RED  1664   // 64*26 per-warp reduce block
#define SFS  28     // final reduce row stride

// Scratch for x-projections: pre[m][n], m = b*T + t, n = gate*1024 + j
__device__ float g_pre[(size_t)BSZ * TT * H3];
// Per-step scratch: (r .* h) for the hbar matmul
__device__ float g_rh[(size_t)BSZ * HID];

// grid barrier state — separate 128B lines
__device__ __align__(128) unsigned g_count_arr[32];
__device__ __align__(128) unsigned g_gen_arr[32];

// ---------- helpers ----------
__device__ __forceinline__ float sigmoidf_(float v) {
    return 1.0f / (1.0f + expf(-v));
}
__device__ __forceinline__ uint32_t cvt_tf32(float x) {
    uint32_t r;
    asm("cvt.rna.tf32.f32 %0, %1;" : "=r"(r) : "f"(x));
    return r;
}
__device__ __forceinline__ void mma_tf32(float* c, const uint32_t* a,
                                         const uint32_t* b) {
    asm volatile(
        "mma.sync.aligned.m16n8k8.row.col.f32.tf32.tf32.f32 "
        "{%0,%1,%2,%3}, {%4,%5,%6,%7}, {%8,%9}, {%0,%1,%2,%3};"
        : "+f"(c[0]), "+f"(c[1]), "+f"(c[2]), "+f"(c[3])
        : "r"(a[0]), "r"(a[1]), "r"(a[2]), "r"(a[3]),
          "r"(b[0]), "r"(b[1]));
}
__device__ __forceinline__ unsigned ld_acq(const unsigned* p) {
    unsigned v;
    asm volatile("ld.acquire.gpu.global.u32 %0, [%1];" : "=r"(v) : "l"(p));
    return v;
}
__device__ __forceinline__ void st_rel(unsigned* p, unsigned v) {
    asm volatile("st.release.gpu.global.u32 [%0], %1;" :: "l"(p), "r"(v));
}
__device__ __forceinline__ void cpasync16(uint32_t saddr, const void* gaddr) {
    asm volatile("cp.async.cg.shared.global [%0], [%1], 16;"
                 :: "r"(saddr), "l"(gaddr));
}
__device__ __forceinline__ void cpcommit() {
    asm volatile("cp.async.commit_group;");
}
template <int N> __device__ __forceinline__ void cpwait() {
    asm volatile("cp.async.wait_group %0;" :: "n"(N));
}

__device__ __forceinline__ void gsync() {
    __syncthreads();
    if (threadIdx.x == 0) {
        __threadfence();
        const unsigned my = ld_acq(&g_gen_arr[0]);
        if (atomicAdd(&g_count_arr[0], 1) == NBLK - 1) {
            g_count_arr[0] = 0;
            st_rel(&g_gen_arr[0], my + 1);
        } else {
            while (ld_acq(&g_gen_arr[0]) == my) { }
        }
    }
    __syncthreads();
}

extern __shared__ float smem_dyn[];

// =====================================================================
// Kernel 1: x projections (tf32 mma.sync) — unchanged from R7.
// =====================================================================
__global__ __launch_bounds__(256) void xproj_kernel(
    const float* __restrict__ x,
    const float* __restrict__ wz, const float* __restrict__ wr,
    const float* __restrict__ wh,
    const float* __restrict__ bz, const float* __restrict__ br,
    const float* __restrict__ bh, int m_off)
{
    float* sx  = smem_dyn;                 // [2][64][XS]
    float* swt = smem_dyn + 2 * 64 * XS;   // [2][64][XS]

    const int tid = threadIdx.x;
    const int n0  = blockIdx.x * 64;
    const int m0  = (m_off + blockIdx.y) * 64;

    const int gate = n0 >> 10;
    const int ng   = n0 & 1023;
    const float* wptr = (gate == 0) ? wz : (gate == 1) ? wr : wh;
    const float* bptr = (gate == 0) ? bz : (gate == 1) ? br : bh;

    const int w  = tid >> 5;
    const int l  = tid & 31;
    const int kw = w >> 2;
    const int mw = (w >> 1) & 1;
    const int nw = w & 1;

    float c[2][4][4];
#pragma unroll
    for (int mt = 0; mt < 2; mt++)
#pragma unroll
        for (int nt = 0; nt < 4; nt++)
#pragma unroll
            for (int r = 0; r < 4; r++) c[mt][nt][r] = 0.0f;

    const int s_row = tid >> 4;
    const int s_q   = tid & 15;

    auto stage = [&](int buf, int k0) {
#pragma unroll
        for (int i = 0; i < 4; i++) {
            int row = s_row + 16 * i;
            uint32_t sa = (uint32_t)__cvta_generic_to_shared(
                sx + buf * 64 * XS + row * XS + 4 * s_q);
            cpasync16(sa, x + (size_t)(m0 + row) * FEAT + k0 + 4 * s_q);
        }
#pragma unroll
        for (int i = 0; i < 4; i++) {
            int kr = s_row + 16 * i;
            uint32_t sa = (uint32_t)__cvta_generic_to_shared(
                swt + buf * 64 * XS + kr * XS + 4 * s_q);
            cpasync16(sa, wptr + (size_t)(1024 + k0 + kr) * HID + ng + 4 * s_q);
        }
        cpcommit();
    };

    const int ar = l >> 2, ac = l & 3;
    const int bk = l & 3,  bn = l >> 2;

    stage(0, 0);
    for (int ch = 0; ch < FEAT / XCHK; ch++) {
        if (ch + 1 < FEAT / XCHK) {
            stage((ch + 1) & 1, (ch + 1) * XCHK);
            cpwait<1>();
        } else {
            cpwait<0>();
        }
        __syncthreads();

        const float* SX = sx  + (ch & 1) * 64 * XS;
        const float* SW = swt + (ch & 1) * 64 * XS;

#pragma unroll
        for (int kt = 0; kt < 4; kt++) {
            const int k = kw * 32 + kt * 8;

            uint32_t a[2][4];
#pragma unroll
            for (int mt = 0; mt < 2; mt++) {
                const float* P = SX + (mw * 32 + mt * 16 + ar) * XS + k + ac;
                a[mt][0] = cvt_tf32(P[0]);
                a[mt][1] = cvt_tf32(P[8 * XS]);
                a[mt][2] = cvt_tf32(P[4]);
                a[mt][3] = cvt_tf32(P[8 * XS + 4]);
            }
            uint32_t b[4][2];
#pragma unroll
            for (int nt = 0; nt < 4; nt++) {
                const float* Q = SW + (k + bk) * XS + nw * 32 + nt * 8 + bn;
                b[nt][0] = cvt_tf32(Q[0]);
                b[nt][1] = cvt_tf32(Q[4 * XS]);
            }
#pragma unroll
            for (int mt = 0; mt < 2; mt++)
#pragma unroll
                for (int nt = 0; nt < 4; nt++)
                    mma_tf32(c[mt][nt], a[mt], b[nt]);
        }
        __syncthreads();
    }

    float* sred = smem_dyn;
    if (kw == 1) {
        float* dst = sred + (mw * 2 + nw) * 1024;
#pragma unroll
        for (int mt = 0; mt < 2; mt++)
#pragma unroll
            for (int nt = 0; nt < 4; nt++)
#pragma unroll
                for (int r = 0; r < 4; r++) {
                    int row = mt * 16 + (l >> 2) + (r >= 2 ? 8 : 0);
                    int col = nt * 8 + 2 * (l & 3) + (r & 1);
                    dst[row * 32 + col] = c[mt][nt][r];
                }
    }
    __syncthreads();
    if (kw == 0) {
        const float* src = sred + (mw * 2 + nw) * 1024;
#pragma unroll
        for (int mt = 0; mt < 2; mt++)
#pragma unroll
            for (int nt = 0; nt < 4; nt++) {
#pragma unroll
                for (int r = 0; r < 4; r++) {
                    int row = mt * 16 + (l >> 2) + (r >= 2 ? 8 : 0);
                    int col = nt * 8 + 2 * (l & 3) + (r & 1);
                    c[mt][nt][r] += src[row * 32 + col];
                }
#pragma unroll
                for (int half = 0; half < 2; half++) {
                    const int row = mt * 16 + (l >> 2) + 8 * half;
                    const int nbase = nw * 32 + nt * 8 + 2 * (l & 3);
                    float2 v;
                    v.x = c[mt][nt][2 * half + 0] + bptr[ng + nbase];
                    v.y = c[mt][nt][2 * half + 1] + bptr[ng + nbase + 1];
                    *(float2*)&g_pre[(size_t)(m0 + mw * 32 + row) * H3 + n0 + nbase] = v;
                }
            }
    }
}

// =====================================================================
// Kernel 2: persistent recurrence, tensor-core, register-resident weights.
// 128 blocks x 256 threads (8 warps). Block owns 8 h-cols.
// Warp w = k-slice [128w, 128w+128). B-frags (tf32) loaded ONCE.
// Per phase: stage h (4 m-chunks of 16 rows, full k, double-buffered)
//            -> mma -> smem k-reduce -> elementwise.
// =====================================================================
__global__ __launch_bounds__(256, 1) void recur_kernel(
    const float* __restrict__ h0,
    const float* __restrict__ wz, const float* __restrict__ wr,
    const float* __restrict__ wh,
    float* __restrict__ out)
{
    float* sA   = smem_dyn;                   // [2][MR][AST]
    float* sred = smem_dyn + 2 * MR * AST;    // [8][64][26]
    float* sfin = sred + 8 * RED;             // [64][SFS]

    const int tid = threadIdx.x;
    const int w   = tid >> 5;
    const int l   = tid & 31;
    const int j0  = blockIdx.x * 8;

    const int ar = l >> 2, ac = l & 3;        // A-frag coords
    const int bk = l & 3,  bn = l >> 2;       // B-frag coords

    // ---- one-time: B fragments in registers (tf32) ----
    uint32_t bzf[16][2], brf[16][2], bhf[16][2];
#pragma unroll
    for (int kt = 0; kt < 16; kt++) {
        const int kg = 128 * w + 8 * kt;
        bzf[kt][0] = cvt_tf32(wz[(size_t)(kg + bk) * HID + j0 + bn]);
        bzf[kt][1] = cvt_tf32(wz[(size_t)(kg + bk + 4) * HID + j0 + bn]);
        brf[kt][0] = cvt_tf32(wr[(size_t)(kg + bk) * HID + j0 + bn]);
        brf[kt][1] = cvt_tf32(wr[(size_t)(kg + bk + 4) * HID + j0 + bn]);
        bhf[kt][0] = cvt_tf32(wh[(size_t)(kg + bk) * HID + j0 + bn]);
        bhf[kt][1] = cvt_tf32(wh[(size_t)(kg + bk + 4) * HID + j0 + bn]);
    }

    // elementwise mapping: thread -> (batch eb, cols ec0, ec0+1)
    const int eb  = tid >> 2;
    const int ec0 = (tid & 3) * 2;

    // stage one m-chunk (16 rows x 1024 k) into buffer
    auto stageA = [&](int buf, const float* src, long rstride, int mc) {
        float* dst = sA + buf * MR * AST;
        const float* base = src + (size_t)mc * MR * rstride;
#pragma unroll
        for (int it = 0; it < 16; it++) {
            int idx = tid + it * 256;
            int row = idx >> 8;
            int kq  = idx & 255;
            uint32_t sa = (uint32_t)__cvta_generic_to_shared(dst + row * AST + 4 * kq);
            cpasync16(sa, base + (size_t)row * rstride + 4 * kq);
        }
        cpcommit();
    };

    for (int t = 0; t < TT; t++) {
        const float* hprev = (t == 0) ? h0 : (out + (size_t)(t - 1) * HID);
        const long   hstr  = (t == 0) ? (long)HID : (long)TT * HID;

        // prefetch pointwise operands
        const float* pp = g_pre + (size_t)(eb * TT + t) * H3 + j0 + ec0;
        const float2 xzv = __ldg((const float2*)pp);
        const float2 xrv = __ldg((const float2*)(pp + 1024));
        const float2 xhv = __ldg((const float2*)(pp + 2048));
        const float2 hpv = __ldcg((const float2*)(hprev + (size_t)eb * hstr + j0 + ec0));

        // ================= phase A: z, r =================
        float aZ[4][4], aR[4][4];
#pragma unroll
        for (int mc = 0; mc < 4; mc++)
#pragma unroll
            for (int r = 0; r < 4; r++) { aZ[mc][r] = 0.0f; aR[mc][r] = 0.0f; }

        stageA(0, hprev, hstr, 0);
        for (int mc = 0; mc < 4; mc++) {
            if (mc < 3) { stageA((mc + 1) & 1, hprev, hstr, mc + 1); cpwait<1>(); }
            else        { cpwait<0>(); }
            __syncthreads();

            const float* SA = sA + (mc & 1) * MR * AST;
#pragma unroll
            for (int kt = 0; kt < 16; kt++) {
                const int koff = 128 * w + 8 * kt;
                const float* P = SA + ar * AST + koff + ac;
                uint32_t a[4];
                a[0] = cvt_tf32(P[0]);
                a[1] = cvt_tf32(P[8 * AST]);
                a[2] = cvt_tf32(P[4]);
                a[3] = cvt_tf32(P[8 * AST + 4]);
                mma_tf32(aZ[mc], a, bzf[kt]);
                mma_tf32(aR[mc], a, brf[kt]);
            }
            __syncthreads();
        }

        // k-split reduce: 8 warps -> sred -> sfin[64][16]
        {
            float* dst = sred + w * RED;
#pragma unroll
            for (int mc = 0; mc < 4; mc++) {
                int r0 = mc * 16 + (l >> 2);
                int c0 = 2 * (l & 3);
                dst[r0 * 26 + c0]           = aZ[mc][0];
                dst[r0 * 26 + c0 + 1]       = aZ[mc][1];
                dst[(r0 + 8) * 26 + c0]     = aZ[mc][2];
                dst[(r0 + 8) * 26 + c0 + 1] = aZ[mc][3];
                dst[r0 * 26 + 8 + c0]           = aR[mc][0];
                dst[r0 * 26 + 8 + c0 + 1]       = aR[mc][1];
                dst[(r0 + 8) * 26 + 8 + c0]     = aR[mc][2];
                dst[(r0 + 8) * 26 + 8 + c0 + 1] = aR[mc][3];
            }
        }
        __syncthreads();
#pragma unroll
        for (int i = 0; i < 4; i++) {
            int idx = tid + i * 256;        // 1024 = 64b x 16n
            int b = idx >> 4, n = idx & 15;
            float s = 0.0f;
#pragma unroll
            for (int ww = 0; ww < 8; ww++) s += sred[ww * RED + b * 26 + n];
            sfin[b * SFS + n] = s;
        }
        __syncthreads();

        // elementwise A
        float zv[2], rhv[2];
        {
            const float hp[2] = {hpv.x, hpv.y};
            const float xz[2] = {xzv.x, xzv.y};
            const float xr[2] = {xrv.x, xrv.y};
            float2 rhst;
#pragma unroll
            for (int j = 0; j < 2; j++) {
                const int c = ec0 + j;
                const float z = sigmoidf_(sfin[eb * SFS + c] + xz[j]);
                const float r = sigmoidf_(sfin[eb * SFS + 8 + c] + xr[j]);
                zv[j] = z;
                rhv[j] = r * hp[j];
            }
            rhst.x = rhv[0]; rhst.y = rhv[1];
            *(float2*)&g_rh[(size_t)eb * HID + j0 + ec0] = rhst;
        }

        gsync();   // rh complete

        // ================= phase B: hbar =================
        float aH[4][4];
#pragma unroll
        for (int mc = 0; mc < 4; mc++)
#pragma unroll
            for (int r = 0; r < 4; r++) aH[mc][r] = 0.0f;

        stageA(0, g_rh, HID, 0);
        for (int mc = 0; mc < 4; mc++) {
            if (mc < 3) { stageA((mc + 1) & 1, g_rh, HID, mc + 1); cpwait<1>(); }
            else        { cpwait<0>(); }
            __syncthreads();

            const float* SA = sA + (mc & 1) * MR * AST;
#pragma unroll
            for (int kt = 0; kt < 16; kt++) {
                const int koff = 128 * w + 8 * kt;
                const float* P = SA + ar * AST + koff + ac;
                uint32_t a[4];
                a[0] = cvt_tf32(P[0]);
                a[1] = cvt_tf32(P[8 * AST]);
                a[2] = cvt_tf32(P[4]);
                a[3] = cvt_tf32(P[8 * AST + 4]);
                mma_tf32(aH[mc], a, bhf[kt]);
            }
            __syncthreads();
        }

        {
            float* dst = sred + w * RED;
#pragma unroll
            for (int mc = 0; mc < 4; mc++) {
                int r0 = mc * 16 + (l >> 2);
                int c0 = 2 * (l & 3);
                dst[r0 * 26 + c0]           = aH[mc][0];
                dst[r0 * 26 + c0 + 1]       = aH[mc][1];
                dst[(r0 + 8) * 26 + c0]     = aH[mc][2];
                dst[(r0 + 8) * 26 + c0 + 1] = aH[mc][3];
            }
        }
        __syncthreads();
#pragma unroll
        for (int i = 0; i < 2; i++) {
            int idx = tid + i * 256;        // 512 = 64b x 8n
            int b = idx >> 3, n = idx & 7;
            float s = 0.0f;
#pragma unroll
            for (int ww = 0; ww < 8; ww++) s += sred[ww * RED + b * 26 + n];
            sfin[b * SFS + n] = s;
        }
        __syncthreads();

        // elementwise B + output
        {
            const float hp[2] = {hpv.x, hpv.y};
            const float xh[2] = {xhv.x, xhv.y};
            float2 o;
            float hn[2];
#pragma unroll
            for (int j = 0; j < 2; j++) {
                const int c = ec0 + j;
                const float hb = tanhf(sfin[eb * SFS + c] + xh[j]);
                hn[j] = (1.0f - zv[j]) * hp[j] + zv[j] * hb;
            }
            o.x = hn[0]; o.y = hn[1];
            *(float2*)&out[((size_t)eb * TT + t) * HID + j0 + ec0] = o;
            if (t == TT - 1)
                *(float2*)&out[(size_t)BSZ * TT * HID + (size_t)eb * HID + j0 + ec0] = o;
        }

        gsync();   // out[:,t,:] complete
    }
}

// =====================================================================
extern "C" void kernel_launch(void* const* d_in, const int* in_sizes, int n_in,
                              void* d_out, int out_size)
{
    const float* x  = (const float*)d_in[0];
    const float* h0 = (const float*)d_in[1];
    const float* wz = (const float*)d_in[2];
    const float* wr = (const float*)d_in[3];
    const float* wh = (const float*)d_in[4];
    const float* bz = (const float*)d_in[5];
    const float* br = (const float*)d_in[6];
    const float* bh = (const float*)d_in[7];
    float* out = (float*)d_out;

    const int x_smem = 4 * 64 * XS * sizeof(float);
    const int r_smem = (2 * MR * AST + 8 * RED + 64 * SFS) * sizeof(float);
    static bool attr_set = false;
    if (!attr_set) {
        cudaFuncSetAttribute(xproj_kernel,
                             cudaFuncAttributeMaxDynamicSharedMemorySize, x_smem);
        cudaFuncSetAttribute(recur_kernel,
                             cudaFuncAttributeMaxDynamicSharedMemorySize, r_smem);
        attr_set = true;
    }

    const int ysplit[4] = {0, 171, 342, 512};
    for (int s = 0; s < 3; s++) {
        dim3 g1(H3 / 64, ysplit[s + 1] - ysplit[s]);
        xproj_kernel<<<g1, 256, x_smem>>>(x, wz, wr, wh, bz, br, bh, ysplit[s]);
    }

    recur_kernel<<<NBLK, 256, r_smem>>>(h0, wz, wr, wh, out);
}

// round 9
// speedup vs baseline: 3.6421x; 1.3324x over previous
#include <cuda_runtime.h>
#include <cuda_bf16.h>
#include <cstdint>
#include <cstddef>

#define BSZ  64
#define TT   512
#define FEAT 1024
#define HID  1024
#define H3   3072
#define NBLK 128

#define XCHK 64     // xproj k-chunk
#define XS   68     // xproj smem row stride

#define AST2 516    // recur staged-A row stride (u32 units), conflict-free
#define RED  1664   // 64*26 per-warp reduce block
#define SFS  28     // final reduce row stride

// Scratch for x-projections: pre[m][n]
__device__ float g_pre[(size_t)BSZ * TT * H3];
// bf16 shadow state: h and (r.*h), packed 2 per u32
__device__ uint32_t g_hb [(size_t)BSZ * HID / 2];
__device__ uint32_t g_rhb[(size_t)BSZ * HID / 2];

// grid barrier state — separate 128B lines
__device__ __align__(128) unsigned g_count_arr[32];
__device__ __align__(128) unsigned g_gen_arr[32];

// ---------- helpers ----------
__device__ __forceinline__ float sigmoidf_(float v) {
    return 1.0f / (1.0f + expf(-v));
}
__device__ __forceinline__ uint32_t cvt_tf32(float x) {
    uint32_t r;
    asm("cvt.rna.tf32.f32 %0, %1;" : "=r"(r) : "f"(x));
    return r;
}
__device__ __forceinline__ uint32_t pack_bf16(float lo, float hi) {
    __nv_bfloat162 v = __floats2bfloat162_rn(lo, hi);
    return *reinterpret_cast<uint32_t*>(&v);
}
__device__ __forceinline__ void mma_tf32(float* c, const uint32_t* a,
                                         const uint32_t* b) {
    asm volatile(
        "mma.sync.aligned.m16n8k8.row.col.f32.tf32.tf32.f32 "
        "{%0,%1,%2,%3}, {%4,%5,%6,%7}, {%8,%9}, {%0,%1,%2,%3};"
        : "+f"(c[0]), "+f"(c[1]), "+f"(c[2]), "+f"(c[3])
        : "r"(a[0]), "r"(a[1]), "r"(a[2]), "r"(a[3]),
          "r"(b[0]), "r"(b[1]));
}
__device__ __forceinline__ void mma_bf16(float* c, const uint32_t* a,
                                         const uint32_t* b) {
    asm volatile(
        "mma.sync.aligned.m16n8k16.row.col.f32.bf16.bf16.f32 "
        "{%0,%1,%2,%3}, {%4,%5,%6,%7}, {%8,%9}, {%0,%1,%2,%3};"
        : "+f"(c[0]), "+f"(c[1]), "+f"(c[2]), "+f"(c[3])
        : "r"(a[0]), "r"(a[1]), "r"(a[2]), "r"(a[3]),
          "r"(b[0]), "r"(b[1]));
}
__device__ __forceinline__ unsigned ld_acq(const unsigned* p) {
    unsigned v;
    asm volatile("ld.acquire.gpu.global.u32 %0, [%1];" : "=r"(v) : "l"(p));
    return v;
}
__device__ __forceinline__ void st_rel(unsigned* p, unsigned v) {
    asm volatile("st.release.gpu.global.u32 [%0], %1;" :: "l"(p), "r"(v));
}
__device__ __forceinline__ void cpasync16(uint32_t saddr, const void* gaddr) {
    asm volatile("cp.async.cg.shared.global [%0], [%1], 16;"
                 :: "r"(saddr), "l"(gaddr));
}
__device__ __forceinline__ void cpcommit() {
    asm volatile("cp.async.commit_group;");
}
template <int N> __device__ __forceinline__ void cpwait() {
    asm volatile("cp.async.wait_group %0;" :: "n"(N));
}

__device__ __forceinline__ void gsync() {
    __syncthreads();
    if (threadIdx.x == 0) {
        __threadfence();
        const unsigned my = ld_acq(&g_gen_arr[0]);
        if (atomicAdd(&g_count_arr[0], 1) == NBLK - 1) {
            g_count_arr[0] = 0;
            st_rel(&g_gen_arr[0], my + 1);
        } else {
            while (ld_acq(&g_gen_arr[0]) == my) { }
        }
    }
    __syncthreads();
}

extern __shared__ float smem_dyn[];

// =====================================================================
// Kernel 1: x projections (tf32 mma.sync) — unchanged from R8.
// =====================================================================
__global__ __launch_bounds__(256) void xproj_kernel(
    const float* __restrict__ x,
    const float* __restrict__ wz, const float* __restrict__ wr,
    const float* __restrict__ wh,
    const float* __restrict__ bz, const float* __restrict__ br,
    const float* __restrict__ bh, int m_off)
{
    float* sx  = smem_dyn;                 // [2][64][XS]
    float* swt = smem_dyn + 2 * 64 * XS;   // [2][64][XS]

    const int tid = threadIdx.x;
    const int n0  = blockIdx.x * 64;
    const int m0  = (m_off + blockIdx.y) * 64;

    const int gate = n0 >> 10;
    const int ng   = n0 & 1023;
    const float* wptr = (gate == 0) ? wz : (gate == 1) ? wr : wh;
    const float* bptr = (gate == 0) ? bz : (gate == 1) ? br : bh;

    const int w  = tid >> 5;
    const int l  = tid & 31;
    const int kw = w >> 2;
    const int mw = (w >> 1) & 1;
    const int nw = w & 1;

    float c[2][4][4];
#pragma unroll
    for (int mt = 0; mt < 2; mt++)
#pragma unroll
        for (int nt = 0; nt < 4; nt++)
#pragma unroll
            for (int r = 0; r < 4; r++) c[mt][nt][r] = 0.0f;

    const int s_row = tid >> 4;
    const int s_q   = tid & 15;

    auto stage = [&](int buf, int k0) {
#pragma unroll
        for (int i = 0; i < 4; i++) {
            int row = s_row + 16 * i;
            uint32_t sa = (uint32_t)__cvta_generic_to_shared(
                sx + buf * 64 * XS + row * XS + 4 * s_q);
            cpasync16(sa, x + (size_t)(m0 + row) * FEAT + k0 + 4 * s_q);
        }
#pragma unroll
        for (int i = 0; i < 4; i++) {
            int kr = s_row + 16 * i;
            uint32_t sa = (uint32_t)__cvta_generic_to_shared(
                swt + buf * 64 * XS + kr * XS + 4 * s_q);
            cpasync16(sa, wptr + (size_t)(1024 + k0 + kr) * HID + ng + 4 * s_q);
        }
        cpcommit();
    };

    const int ar = l >> 2, ac = l & 3;
    const int bk = l & 3,  bn = l >> 2;

    stage(0, 0);
    for (int ch = 0; ch < FEAT / XCHK; ch++) {
        if (ch + 1 < FEAT / XCHK) {
            stage((ch + 1) & 1, (ch + 1) * XCHK);
            cpwait<1>();
        } else {
            cpwait<0>();
        }
        __syncthreads();

        const float* SX = sx  + (ch & 1) * 64 * XS;
        const float* SW = swt + (ch & 1) * 64 * XS;

#pragma unroll
        for (int kt = 0; kt < 4; kt++) {
            const int k = kw * 32 + kt * 8;

            uint32_t a[2][4];
#pragma unroll
            for (int mt = 0; mt < 2; mt++) {
                const float* P = SX + (mw * 32 + mt * 16 + ar) * XS + k + ac;
                a[mt][0] = cvt_tf32(P[0]);
                a[mt][1] = cvt_tf32(P[8 * XS]);
                a[mt][2] = cvt_tf32(P[4]);
                a[mt][3] = cvt_tf32(P[8 * XS + 4]);
            }
            uint32_t b[4][2];
#pragma unroll
            for (int nt = 0; nt < 4; nt++) {
                const float* Q = SW + (k + bk) * XS + nw * 32 + nt * 8 + bn;
                b[nt][0] = cvt_tf32(Q[0]);
                b[nt][1] = cvt_tf32(Q[4 * XS]);
            }
#pragma unroll
            for (int mt = 0; mt < 2; mt++)
#pragma unroll
                for (int nt = 0; nt < 4; nt++)
                    mma_tf32(c[mt][nt], a[mt], b[nt]);
        }
        __syncthreads();
    }

    float* sred = smem_dyn;
    if (kw == 1) {
        float* dst = sred + (mw * 2 + nw) * 1024;
#pragma unroll
        for (int mt = 0; mt < 2; mt++)
#pragma unroll
            for (int nt = 0; nt < 4; nt++)
#pragma unroll
                for (int r = 0; r < 4; r++) {
                    int row = mt * 16 + (l >> 2) + (r >= 2 ? 8 : 0);
                    int col = nt * 8 + 2 * (l & 3) + (r & 1);
                    dst[row * 32 + col] = c[mt][nt][r];
                }
    }
    __syncthreads();
    if (kw == 0) {
        const float* src = sred + (mw * 2 + nw) * 1024;
#pragma unroll
        for (int mt = 0; mt < 2; mt++)
#pragma unroll
            for (int nt = 0; nt < 4; nt++) {
#pragma unroll
                for (int r = 0; r < 4; r++) {
                    int row = mt * 16 + (l >> 2) + (r >= 2 ? 8 : 0);
                    int col = nt * 8 + 2 * (l & 3) + (r & 1);
                    c[mt][nt][r] += src[row * 32 + col];
                }
#pragma unroll
                for (int half = 0; half < 2; half++) {
                    const int row = mt * 16 + (l >> 2) + 8 * half;
                    const int nbase = nw * 32 + nt * 8 + 2 * (l & 3);
                    float2 v;
                    v.x = c[mt][nt][2 * half + 0] + bptr[ng + nbase];
                    v.y = c[mt][nt][2 * half + 1] + bptr[ng + nbase + 1];
                    *(float2*)&g_pre[(size_t)(m0 + mw * 32 + row) * H3 + n0 + nbase] = v;
                }
            }
    }
}

// =====================================================================
// Kernel 2: persistent recurrence — bf16 mma (m16n8k16), fp32 state.
// 128 blocks x 256 threads (8 warps), 8 h-cols per block.
// Warp w = k-slice [128w,128w+128). B-frags bf16 in regs (loaded once).
// A operands staged as packed bf16 (g_hb / g_rhb), 2 chunks x 32 rows,
// double-buffered cp.async.
// =====================================================================
__global__ __launch_bounds__(256, 1) void recur_kernel(
    const float* __restrict__ h0,
    const float* __restrict__ wz, const float* __restrict__ wr,
    const float* __restrict__ wh,
    float* __restrict__ out)
{
    uint32_t* sAu  = (uint32_t*)smem_dyn;           // [2][32][AST2]
    float*    sred = smem_dyn + 2 * 32 * AST2;      // [8][64][26]
    float*    sfin = sred + 8 * RED;                // [64][SFS]

    const int tid = threadIdx.x;
    const int w   = tid >> 5;
    const int l   = tid & 31;
    const int j0  = blockIdx.x * 8;

    const int ar = l >> 2, ac = l & 3;        // A-frag coords
    const int bk = l & 3,  bn = l >> 2;       // B-frag coords

    // ---- one-time: bf16 B fragments in registers ----
    uint32_t bzf[8][2], brf[8][2], bhf[8][2];
#pragma unroll
    for (int kt = 0; kt < 8; kt++) {
        const int kg = 128 * w + 16 * kt;
        const int n  = j0 + bn;
#pragma unroll
        for (int h = 0; h < 2; h++) {
            const int k0 = kg + 2 * bk + 8 * h;
            bzf[kt][h] = pack_bf16(wz[(size_t)k0 * HID + n], wz[(size_t)(k0 + 1) * HID + n]);
            brf[kt][h] = pack_bf16(wr[(size_t)k0 * HID + n], wr[(size_t)(k0 + 1) * HID + n]);
            bhf[kt][h] = pack_bf16(wh[(size_t)k0 * HID + n], wh[(size_t)(k0 + 1) * HID + n]);
        }
    }

    // ---- one-time: convert h0 -> bf16 shadow (block-sliced) ----
    {
        const int base = blockIdx.x * 512;        // elems
        const float lo = h0[base + 2 * tid];
        const float hi = h0[base + 2 * tid + 1];
        g_hb[(base >> 1) + tid] = pack_bf16(lo, hi);
    }
    gsync();

    // elementwise mapping: thread -> (batch eb, cols ec0, ec0+1)
    const int eb  = tid >> 2;
    const int ec0 = (tid & 3) * 2;

    // stage one 32-row chunk of packed-bf16 A (32 x 512 u32)
    auto stageA = [&](int buf, const uint32_t* srcu, int mc) {
        uint32_t* dst = sAu + buf * 32 * AST2;
        const uint32_t* base = srcu + (size_t)mc * 32 * 512;
#pragma unroll
        for (int it = 0; it < 16; it++) {
            int idx = tid + it * 256;
            int row = idx >> 7;                   // 0..31
            int q   = idx & 127;                  // 16B quad index
            uint32_t sa = (uint32_t)__cvta_generic_to_shared(dst + row * AST2 + 4 * q);
            cpasync16(sa, base + (size_t)row * 512 + 4 * q);
        }
        cpcommit();
    };

    for (int t = 0; t < TT; t++) {
        const float* hprev = (t == 0) ? h0 : (out + (size_t)(t - 1) * HID);
        const long   hstr  = (t == 0) ? (long)HID : (long)TT * HID;

        // prefetch pointwise operands (fp32)
        const float* pp = g_pre + (size_t)(eb * TT + t) * H3 + j0 + ec0;
        const float2 xzv = __ldg((const float2*)pp);
        const float2 xrv = __ldg((const float2*)(pp + 1024));
        const float2 xhv = __ldg((const float2*)(pp + 2048));
        const float2 hpv = __ldcg((const float2*)(hprev + (size_t)eb * hstr + j0 + ec0));

        // ================= phase A: z, r =================
        float aZ[4][4], aR[4][4];
#pragma unroll
        for (int mt = 0; mt < 4; mt++)
#pragma unroll
            for (int r = 0; r < 4; r++) { aZ[mt][r] = 0.0f; aR[mt][r] = 0.0f; }

        stageA(0, g_hb, 0);
        for (int mc = 0; mc < 2; mc++) {
            if (mc == 0) { stageA(1, g_hb, 1); cpwait<1>(); }
            else         { cpwait<0>(); }
            __syncthreads();

            const uint32_t* SA = sAu + mc * 32 * AST2;
#pragma unroll
            for (int kt = 0; kt < 8; kt++) {
                const int ko = 64 * w + 8 * kt;
#pragma unroll
                for (int sub = 0; sub < 2; sub++) {
                    const uint32_t* P = SA + (16 * sub + ar) * AST2 + ko + ac;
                    uint32_t a[4];
                    a[0] = P[0];
                    a[1] = P[8 * AST2];
                    a[2] = P[4];
                    a[3] = P[8 * AST2 + 4];
                    mma_bf16(aZ[2 * mc + sub], a, bzf[kt]);
                    mma_bf16(aR[2 * mc + sub], a, brf[kt]);
                }
            }
            __syncthreads();
        }

        // k-split reduce: 8 warps -> sred -> sfin[64][16]
        {
            float* dst = sred + w * RED;
#pragma unroll
            for (int mt = 0; mt < 4; mt++) {
                int r0 = mt * 16 + (l >> 2);
                int c0 = 2 * (l & 3);
                dst[r0 * 26 + c0]           = aZ[mt][0];
                dst[r0 * 26 + c0 + 1]       = aZ[mt][1];
                dst[(r0 + 8) * 26 + c0]     = aZ[mt][2];
                dst[(r0 + 8) * 26 + c0 + 1] = aZ[mt][3];
                dst[r0 * 26 + 8 + c0]           = aR[mt][0];
                dst[r0 * 26 + 8 + c0 + 1]       = aR[mt][1];
                dst[(r0 + 8) * 26 + 8 + c0]     = aR[mt][2];
                dst[(r0 + 8) * 26 + 8 + c0 + 1] = aR[mt][3];
            }
        }
        __syncthreads();
#pragma unroll
        for (int i = 0; i < 4; i++) {
            int idx = tid + i * 256;        // 1024 = 64b x 16n
            int b = idx >> 4, n = idx & 15;
            float s = 0.0f;
#pragma unroll
            for (int ww = 0; ww < 8; ww++) s += sred[ww * RED + b * 26 + n];
            sfin[b * SFS + n] = s;
        }
        __syncthreads();

        // elementwise A
        float zv[2];
        {
            const float hp[2] = {hpv.x, hpv.y};
            const float xz[2] = {xzv.x, xzv.y};
            const float xr[2] = {xrv.x, xrv.y};
            float rhv[2];
#pragma unroll
            for (int j = 0; j < 2; j++) {
                const int c = ec0 + j;
                zv[j]  = sigmoidf_(sfin[eb * SFS + c] + xz[j]);
                const float r = sigmoidf_(sfin[eb * SFS + 8 + c] + xr[j]);
                rhv[j] = r * hp[j];
            }
            g_rhb[(size_t)eb * 512 + ((j0 + ec0) >> 1)] = pack_bf16(rhv[0], rhv[1]);
        }

        gsync();   // rh complete

        // ================= phase B: hbar =================
        float aH[4][4];
#pragma unroll
        for (int mt = 0; mt < 4; mt++)
#pragma unroll
            for (int r = 0; r < 4; r++) aH[mt][r] = 0.0f;

        stageA(0, g_rhb, 0);
        for (int mc = 0; mc < 2; mc++) {
            if (mc == 0) { stageA(1, g_rhb, 1); cpwait<1>(); }
            else         { cpwait<0>(); }
            __syncthreads();

            const uint32_t* SA = sAu + mc * 32 * AST2;
#pragma unroll
            for (int kt = 0; kt < 8; kt++) {
                const int ko = 64 * w + 8 * kt;
#pragma unroll
                for (int sub = 0; sub < 2; sub++) {
                    const uint32_t* P = SA + (16 * sub + ar) * AST2 + ko + ac;
                    uint32_t a[4];
                    a[0] = P[0];
                    a[1] = P[8 * AST2];
                    a[2] = P[4];
                    a[3] = P[8 * AST2 + 4];
                    mma_bf16(aH[2 * mc + sub], a, bhf[kt]);
                }
            }
            __syncthreads();
        }

        {
            float* dst = sred + w * RED;
#pragma unroll
            for (int mt = 0; mt < 4; mt++) {
                int r0 = mt * 16 + (l >> 2);
                int c0 = 2 * (l & 3);
                dst[r0 * 26 + c0]           = aH[mt][0];
                dst[r0 * 26 + c0 + 1]       = aH[mt][1];
                dst[(r0 + 8) * 26 + c0]     = aH[mt][2];
                dst[(r0 + 8) * 26 + c0 + 1] = aH[mt][3];
            }
        }
        __syncthreads();
#pragma unroll
        for (int i = 0; i < 2; i++) {
            int idx = tid + i * 256;        // 512 = 64b x 8n
            int b = idx >> 3, n = idx & 7;
            float s = 0.0f;
#pragma unroll
            for (int ww = 0; ww < 8; ww++) s += sred[ww * RED + b * 26 + n];
            sfin[b * SFS + n] = s;
        }
        __syncthreads();

        // elementwise B + output (fp32 state update)
        {
            const float hp[2] = {hpv.x, hpv.y};
            const float xh[2] = {xhv.x, xhv.y};
            float hn[2];
#pragma unroll
            for (int j = 0; j < 2; j++) {
                const int c = ec0 + j;
                const float hb = tanhf(sfin[eb * SFS + c] + xh[j]);
                hn[j] = (1.0f - zv[j]) * hp[j] + zv[j] * hb;
            }
            float2 o; o.x = hn[0]; o.y = hn[1];
            *(float2*)&out[((size_t)eb * TT + t) * HID + j0 + ec0] = o;
            g_hb[(size_t)eb * 512 + ((j0 + ec0) >> 1)] = pack_bf16(hn[0], hn[1]);
            if (t == TT - 1)
                *(float2*)&out[(size_t)BSZ * TT * HID + (size_t)eb * HID + j0 + ec0] = o;
        }

        gsync();   // h complete
    }
}

// =====================================================================
extern "C" void kernel_launch(void* const* d_in, const int* in_sizes, int n_in,
                              void* d_out, int out_size)
{
    const float* x  = (const float*)d_in[0];
    const float* h0 = (const float*)d_in[1];
    const float* wz = (const float*)d_in[2];
    const float* wr = (const float*)d_in[3];
    const float* wh = (const float*)d_in[4];
    const float* bz = (const float*)d_in[5];
    const float* br = (const float*)d_in[6];
    const float* bh = (const float*)d_in[7];
    float* out = (float*)d_out;

    const int x_smem = 4 * 64 * XS * sizeof(float);
    const int r_smem = (2 * 32 * AST2 + 8 * RED + 64 * SFS) * sizeof(float);
    static bool attr_set = false;
    if (!attr_set) {
        cudaFuncSetAttribute(xproj_kernel,
                             cudaFuncAttributeMaxDynamicSharedMemorySize, x_smem);
        cudaFuncSetAttribute(recur_kernel,
                             cudaFuncAttributeMaxDynamicSharedMemorySize, r_smem);
        attr_set = true;
    }

    const int ysplit[4] = {0, 171, 342, 512};
    for (int s = 0; s < 3; s++) {
        dim3 g1(H3 / 64, ysplit[s + 1] - ysplit[s]);
        xproj_kernel<<<g1, 256, x_smem>>>(x, wz, wr, wh, bz, br, bh, ysplit[s]);
    }

    recur_kernel<<<NBLK, 256, r_smem>>>(h0, wz, wr, wh, out);
}

// round 10
// speedup vs baseline: 4.1353x; 1.1354x over previous
#include <cuda_runtime.h>
#include <cuda_bf16.h>
#include <cstdint>
#include <cstddef>

#define BSZ  64
#define TT   512
#define FEAT 1024
#define HID  1024
#define H3   3072

#define XCHK 64     // xproj k-chunk
#define XS   68     // xproj smem row stride

#define AST2 516    // recur staged-A row stride (u32), 516%32=4 -> conflict-free
#define REDW (32*34)  // per-warp reduce block (floats)
#define SFS  34     // final reduce row stride

// Scratch for x-projections: pre[m][n]
__device__ float g_pre[(size_t)BSZ * TT * H3];
// bf16 shadow state: h and (r.*h), packed 2 per u32  [64 rows][512 u32]
__device__ uint32_t g_hb [(size_t)BSZ * HID / 2];
__device__ uint32_t g_rhb[(size_t)BSZ * HID / 2];

// barrier state — per-half barriers on separate 128B lines + init barrier
__device__ __align__(128) unsigned g_count_arr[64];
__device__ __align__(128) unsigned g_gen_arr[64];
__device__ __align__(128) unsigned g_icount[32];
__device__ __align__(128) unsigned g_igen[32];

// ---------- helpers ----------
__device__ __forceinline__ float sigmoidf_(float v) {
    return 1.0f / (1.0f + expf(-v));
}
__device__ __forceinline__ uint32_t cvt_tf32(float x) {
    uint32_t r;
    asm("cvt.rna.tf32.f32 %0, %1;" : "=r"(r) : "f"(x));
    return r;
}
__device__ __forceinline__ uint32_t pack_bf16(float lo, float hi) {
    __nv_bfloat162 v = __floats2bfloat162_rn(lo, hi);
    return *reinterpret_cast<uint32_t*>(&v);
}
__device__ __forceinline__ void mma_tf32(float* c, const uint32_t* a,
                                         const uint32_t* b) {
    asm volatile(
        "mma.sync.aligned.m16n8k8.row.col.f32.tf32.tf32.f32 "
        "{%0,%1,%2,%3}, {%4,%5,%6,%7}, {%8,%9}, {%0,%1,%2,%3};"
        : "+f"(c[0]), "+f"(c[1]), "+f"(c[2]), "+f"(c[3])
        : "r"(a[0]), "r"(a[1]), "r"(a[2]), "r"(a[3]),
          "r"(b[0]), "r"(b[1]));
}
__device__ __forceinline__ void mma_bf16(float* c, const uint32_t* a,
                                         const uint32_t* b) {
    asm volatile(
        "mma.sync.aligned.m16n8k16.row.col.f32.bf16.bf16.f32 "
        "{%0,%1,%2,%3}, {%4,%5,%6,%7}, {%8,%9}, {%0,%1,%2,%3};"
        : "+f"(c[0]), "+f"(c[1]), "+f"(c[2]), "+f"(c[3])
        : "r"(a[0]), "r"(a[1]), "r"(a[2]), "r"(a[3]),
          "r"(b[0]), "r"(b[1]));
}
__device__ __forceinline__ unsigned ld_acq(const unsigned* p) {
    unsigned v;
    asm volatile("ld.acquire.gpu.global.u32 %0, [%1];" : "=r"(v) : "l"(p));
    return v;
}
__device__ __forceinline__ void st_rel(unsigned* p, unsigned v) {
    asm volatile("st.release.gpu.global.u32 [%0], %1;" :: "l"(p), "r"(v));
}
__device__ __forceinline__ void cpasync16(uint32_t saddr, const void* gaddr) {
    asm volatile("cp.async.cg.shared.global [%0], [%1], 16;"
                 :: "r"(saddr), "l"(gaddr));
}
__device__ __forceinline__ void cpcommit() {
    asm volatile("cp.async.commit_group;");
}
template <int N> __device__ __forceinline__ void cpwait() {
    asm volatile("cp.async.wait_group %0;" :: "n"(N));
}

// software barrier over n co-resident blocks
__device__ __forceinline__ void swsync(unsigned* cnt, unsigned* gen, int n) {
    __syncthreads();
    if (threadIdx.x == 0) {
        __threadfence();
        const unsigned my = ld_acq(gen);
        if (atomicAdd(cnt, 1) == (unsigned)(n - 1)) {
            *cnt = 0;
            st_rel(gen, my + 1);
        } else {
            while (ld_acq(gen) == my) { }
        }
    }
    __syncthreads();
}

extern __shared__ float smem_dyn[];

// =====================================================================
// Kernel 1: x projections (tf32 mma.sync) — unchanged from R9.
// =====================================================================
__global__ __launch_bounds__(256) void xproj_kernel(
    const float* __restrict__ x,
    const float* __restrict__ wz, const float* __restrict__ wr,
    const float* __restrict__ wh,
    const float* __restrict__ bz, const float* __restrict__ br,
    const float* __restrict__ bh, int m_off)
{
    float* sx  = smem_dyn;                 // [2][64][XS]
    float* swt = smem_dyn + 2 * 64 * XS;   // [2][64][XS]

    const int tid = threadIdx.x;
    const int n0  = blockIdx.x * 64;
    const int m0  = (m_off + blockIdx.y) * 64;

    const int gate = n0 >> 10;
    const int ng   = n0 & 1023;
    const float* wptr = (gate == 0) ? wz : (gate == 1) ? wr : wh;
    const float* bptr = (gate == 0) ? bz : (gate == 1) ? br : bh;

    const int w  = tid >> 5;
    const int l  = tid & 31;
    const int kw = w >> 2;
    const int mw = (w >> 1) & 1;
    const int nw = w & 1;

    float c[2][4][4];
#pragma unroll
    for (int mt = 0; mt < 2; mt++)
#pragma unroll
        for (int nt = 0; nt < 4; nt++)
#pragma unroll
            for (int r = 0; r < 4; r++) c[mt][nt][r] = 0.0f;

    const int s_row = tid >> 4;
    const int s_q   = tid & 15;

    auto stage = [&](int buf, int k0) {
#pragma unroll
        for (int i = 0; i < 4; i++) {
            int row = s_row + 16 * i;
            uint32_t sa = (uint32_t)__cvta_generic_to_shared(
                sx + buf * 64 * XS + row * XS + 4 * s_q);
            cpasync16(sa, x + (size_t)(m0 + row) * FEAT + k0 + 4 * s_q);
        }
#pragma unroll
        for (int i = 0; i < 4; i++) {
            int kr = s_row + 16 * i;
            uint32_t sa = (uint32_t)__cvta_generic_to_shared(
                swt + buf * 64 * XS + kr * XS + 4 * s_q);
            cpasync16(sa, wptr + (size_t)(1024 + k0 + kr) * HID + ng + 4 * s_q);
        }
        cpcommit();
    };

    const int ar = l >> 2, ac = l & 3;
    const int bk = l & 3,  bn = l >> 2;

    stage(0, 0);
    for (int ch = 0; ch < FEAT / XCHK; ch++) {
        if (ch + 1 < FEAT / XCHK) {
            stage((ch + 1) & 1, (ch + 1) * XCHK);
            cpwait<1>();
        } else {
            cpwait<0>();
        }
        __syncthreads();

        const float* SX = sx  + (ch & 1) * 64 * XS;
        const float* SW = swt + (ch & 1) * 64 * XS;

#pragma unroll
        for (int kt = 0; kt < 4; kt++) {
            const int k = kw * 32 + kt * 8;

            uint32_t a[2][4];
#pragma unroll
            for (int mt = 0; mt < 2; mt++) {
                const float* P = SX + (mw * 32 + mt * 16 + ar) * XS + k + ac;
                a[mt][0] = cvt_tf32(P[0]);
                a[mt][1] = cvt_tf32(P[8 * XS]);
                a[mt][2] = cvt_tf32(P[4]);
                a[mt][3] = cvt_tf32(P[8 * XS + 4]);
            }
            uint32_t b[4][2];
#pragma unroll
            for (int nt = 0; nt < 4; nt++) {
                const float* Q = SW + (k + bk) * XS + nw * 32 + nt * 8 + bn;
                b[nt][0] = cvt_tf32(Q[0]);
                b[nt][1] = cvt_tf32(Q[4 * XS]);
            }
#pragma unroll
            for (int mt = 0; mt < 2; mt++)
#pragma unroll
                for (int nt = 0; nt < 4; nt++)
                    mma_tf32(c[mt][nt], a[mt], b[nt]);
        }
        __syncthreads();
    }

    float* sred = smem_dyn;
    if (kw == 1) {
        float* dst = sred + (mw * 2 + nw) * 1024;
#pragma unroll
        for (int mt = 0; mt < 2; mt++)
#pragma unroll
            for (int nt = 0; nt < 4; nt++)
#pragma unroll
                for (int r = 0; r < 4; r++) {
                    int row = mt * 16 + (l >> 2) + (r >= 2 ? 8 : 0);
                    int col = nt * 8 + 2 * (l & 3) + (r & 1);
                    dst[row * 32 + col] = c[mt][nt][r];
                }
    }
    __syncthreads();
    if (kw == 0) {
        const float* src = sred + (mw * 2 + nw) * 1024;
#pragma unroll
        for (int mt = 0; mt < 2; mt++)
#pragma unroll
            for (int nt = 0; nt < 4; nt++) {
#pragma unroll
                for (int r = 0; r < 4; r++) {
                    int row = mt * 16 + (l >> 2) + (r >= 2 ? 8 : 0);
                    int col = nt * 8 + 2 * (l & 3) + (r & 1);
                    c[mt][nt][r] += src[row * 32 + col];
                }
#pragma unroll
                for (int half = 0; half < 2; half++) {
                    const int row = mt * 16 + (l >> 2) + 8 * half;
                    const int nbase = nw * 32 + nt * 8 + 2 * (l & 3);
                    float2 v;
                    v.x = c[mt][nt][2 * half + 0] + bptr[ng + nbase];
                    v.y = c[mt][nt][2 * half + 1] + bptr[ng + nbase + 1];
                    *(float2*)&g_pre[(size_t)(m0 + mw * 32 + row) * H3 + n0 + nbase] = v;
                }
            }
    }
}

// =====================================================================
// Kernel 2: persistent recurrence — bf16 mma, batch-split grid.
// 128 blocks = 2 batch-halves x 64 col-groups (16 cols).
// Per block: 32 batch rows x 16 cols. 8 warps = 8-way k-split.
// Per-half barriers (64 blocks) — the two halves run decoupled.
// A operand (32x1024 bf16 = 66KB) staged in ONE cp.async round per phase.
// =====================================================================
__global__ __launch_bounds__(256, 1) void recur_kernel(
    const float* __restrict__ h0,
    const float* __restrict__ wz, const float* __restrict__ wr,
    const float* __restrict__ wh,
    float* __restrict__ out)
{
    uint32_t* sAu  = (uint32_t*)smem_dyn;           // [32][AST2]
    float*    sred = smem_dyn + 32 * AST2;          // [8][32][34]
    float*    sfin = sred + 8 * REDW;               // [32][34]

    const int tid  = threadIdx.x;
    const int w    = tid >> 5;
    const int l    = tid & 31;
    const int half = blockIdx.x & 1;
    const int cg   = blockIdx.x >> 1;          // 0..63
    const int j0   = cg * 16;

    unsigned* bcnt = &g_count_arr[half * 32];
    unsigned* bgen = &g_gen_arr[half * 32];

    const int ar = l >> 2, ac = l & 3;        // A-frag coords
    const int bk = l & 3,  bn = l >> 2;       // B-frag coords

    // ---- one-time: bf16 B fragments in registers (k-slice 128w, n=16) ----
    uint32_t bzf[8][2][2], brf[8][2][2], bhf[8][2][2];
#pragma unroll
    for (int kt = 0; kt < 8; kt++)
#pragma unroll
        for (int nt = 0; nt < 2; nt++)
#pragma unroll
            for (int h = 0; h < 2; h++) {
                const int k0 = 128 * w + 16 * kt + 2 * bk + 8 * h;
                const int n  = j0 + 8 * nt + bn;
                bzf[kt][nt][h] = pack_bf16(wz[(size_t)k0 * HID + n], wz[(size_t)(k0 + 1) * HID + n]);
                brf[kt][nt][h] = pack_bf16(wr[(size_t)k0 * HID + n], wr[(size_t)(k0 + 1) * HID + n]);
                bhf[kt][nt][h] = pack_bf16(wh[(size_t)k0 * HID + n], wh[(size_t)(k0 + 1) * HID + n]);
            }

    // ---- one-time: h0 -> bf16 shadow, then full-grid barrier ----
    {
        const int idx = blockIdx.x * 256 + tid;    // 32768 u32 total
        g_hb[idx] = pack_bf16(h0[2 * idx], h0[2 * idx + 1]);
    }
    swsync(&g_icount[0], &g_igen[0], 128);

    // elementwise mapping: thread -> (local row eb 0..31, cols ec0, ec0+1)
    const int eb  = tid >> 3;
    const int ec0 = (tid & 7) * 2;
    const int gb  = half * 32 + eb;            // global batch row

    // stage this half's 32x1024 bf16 rows (16384 u32) in one round
    auto stageA = [&](const uint32_t* srcu) {
        const uint32_t* base = srcu + (size_t)half * 32 * 512;
#pragma unroll
        for (int it = 0; it < 16; it++) {
            int idx = tid + it * 256;
            int row = idx >> 7;                // 0..31
            int q   = idx & 127;               // 16B quad index
            uint32_t sa = (uint32_t)__cvta_generic_to_shared(sAu + row * AST2 + 4 * q);
            cpasync16(sa, base + (size_t)row * 512 + 4 * q);
        }
        cpcommit();
    };

    for (int t = 0; t < TT; t++) {
        const float* hprev = (t == 0) ? h0 : (out + (size_t)(t - 1) * HID);
        const long   hstr  = (t == 0) ? (long)HID : (long)TT * HID;

        // prefetch pointwise operands (fp32)
        const float* pp = g_pre + (size_t)(gb * TT + t) * H3 + j0 + ec0;
        const float2 xzv = __ldg((const float2*)pp);
        const float2 xrv = __ldg((const float2*)(pp + 1024));
        const float2 xhv = __ldg((const float2*)(pp + 2048));
        const float2 hpv = __ldcg((const float2*)(hprev + (size_t)gb * hstr + j0 + ec0));

        // ================= phase A: z, r =================
        float aZ[2][2][4], aR[2][2][4];
#pragma unroll
        for (int mt = 0; mt < 2; mt++)
#pragma unroll
            for (int nt = 0; nt < 2; nt++)
#pragma unroll
                for (int r = 0; r < 4; r++) { aZ[mt][nt][r] = 0.0f; aR[mt][nt][r] = 0.0f; }

        stageA(g_hb);
        cpwait<0>();
        __syncthreads();

#pragma unroll
        for (int kt = 0; kt < 8; kt++) {
            const int ko = 64 * w + 8 * kt;
#pragma unroll
            for (int mt = 0; mt < 2; mt++) {
                const uint32_t* P = sAu + (16 * mt + ar) * AST2 + ko + ac;
                uint32_t a[4];
                a[0] = P[0];
                a[1] = P[8 * AST2];
                a[2] = P[4];
                a[3] = P[8 * AST2 + 4];
#pragma unroll
                for (int nt = 0; nt < 2; nt++) {
                    mma_bf16(aZ[mt][nt], a, bzf[kt][nt]);
                    mma_bf16(aR[mt][nt], a, brf[kt][nt]);
                }
            }
        }
        __syncthreads();   // done with sAu

        // k-split reduce: 8 warps -> sred -> sfin[32][32] (z:0..15, r:16..31)
        {
            float* dst = sred + w * REDW;
#pragma unroll
            for (int mt = 0; mt < 2; mt++)
#pragma unroll
                for (int nt = 0; nt < 2; nt++) {
                    int r0 = 16 * mt + (l >> 2);
                    int c0 = 8 * nt + 2 * (l & 3);
                    dst[r0 * 34 + c0]            = aZ[mt][nt][0];
                    dst[r0 * 34 + c0 + 1]        = aZ[mt][nt][1];
                    dst[(r0 + 8) * 34 + c0]      = aZ[mt][nt][2];
                    dst[(r0 + 8) * 34 + c0 + 1]  = aZ[mt][nt][3];
                    dst[r0 * 34 + 16 + c0]           = aR[mt][nt][0];
                    dst[r0 * 34 + 16 + c0 + 1]       = aR[mt][nt][1];
                    dst[(r0 + 8) * 34 + 16 + c0]     = aR[mt][nt][2];
                    dst[(r0 + 8) * 34 + 16 + c0 + 1] = aR[mt][nt][3];
                }
        }
        __syncthreads();
#pragma unroll
        for (int i = 0; i < 4; i++) {
            int idx = tid + i * 256;        // 1024 = 32 rows x 32 cols
            int b = idx >> 5, n = idx & 31;
            float s = 0.0f;
#pragma unroll
            for (int ww = 0; ww < 8; ww++) s += sred[ww * REDW + b * 34 + n];
            sfin[b * SFS + n] = s;
        }
        __syncthreads();

        // elementwise A: z, rh
        float zv[2];
        {
            const float hp[2] = {hpv.x, hpv.y};
            const float xz[2] = {xzv.x, xzv.y};
            const float xr[2] = {xrv.x, xrv.y};
            float rhv[2];
#pragma unroll
            for (int j = 0; j < 2; j++) {
                zv[j] = sigmoidf_(sfin[eb * SFS + ec0 + j] + xz[j]);
                const float r = sigmoidf_(sfin[eb * SFS + 16 + ec0 + j] + xr[j]);
                rhv[j] = r * hp[j];
            }
            g_rhb[(size_t)gb * 512 + ((j0 + ec0) >> 1)] = pack_bf16(rhv[0], rhv[1]);
        }

        swsync(bcnt, bgen, 64);   // rh complete (this half only)

        // ================= phase B: hbar =================
        float aH[2][2][4];
#pragma unroll
        for (int mt = 0; mt < 2; mt++)
#pragma unroll
            for (int nt = 0; nt < 2; nt++)
#pragma unroll
                for (int r = 0; r < 4; r++) aH[mt][nt][r] = 0.0f;

        stageA(g_rhb);
        cpwait<0>();
        __syncthreads();

#pragma unroll
        for (int kt = 0; kt < 8; kt++) {
            const int ko = 64 * w + 8 * kt;
#pragma unroll
            for (int mt = 0; mt < 2; mt++) {
                const uint32_t* P = sAu + (16 * mt + ar) * AST2 + ko + ac;
                uint32_t a[4];
                a[0] = P[0];
                a[1] = P[8 * AST2];
                a[2] = P[4];
                a[3] = P[8 * AST2 + 4];
#pragma unroll
                for (int nt = 0; nt < 2; nt++)
                    mma_bf16(aH[mt][nt], a, bhf[kt][nt]);
            }
        }
        __syncthreads();

        {
            float* dst = sred + w * REDW;
#pragma unroll
            for (int mt = 0; mt < 2; mt++)
#pragma unroll
                for (int nt = 0; nt < 2; nt++) {
                    int r0 = 16 * mt + (l >> 2);
                    int c0 = 8 * nt + 2 * (l & 3);
                    dst[r0 * 34 + c0]           = aH[mt][nt][0];
                    dst[r0 * 34 + c0 + 1]       = aH[mt][nt][1];
                    dst[(r0 + 8) * 34 + c0]     = aH[mt][nt][2];
                    dst[(r0 + 8) * 34 + c0 + 1] = aH[mt][nt][3];
                }
        }
        __syncthreads();
#pragma unroll
        for (int i = 0; i < 2; i++) {
            int idx = tid + i * 256;        // 512 = 32 rows x 16 cols
            int b = idx >> 4, n = idx & 15;
            float s = 0.0f;
#pragma unroll
            for (int ww = 0; ww < 8; ww++) s += sred[ww * REDW + b * 34 + n];
            sfin[b * SFS + n] = s;
        }
        __syncthreads();

        // elementwise B + output (fp32 state update)
        {
            const float hp[2] = {hpv.x, hpv.y};
            const float xh[2] = {xhv.x, xhv.y};
            float hn[2];
#pragma unroll
            for (int j = 0; j < 2; j++) {
                const float hb = tanhf(sfin[eb * SFS + ec0 + j] + xh[j]);
                hn[j] = (1.0f - zv[j]) * hp[j] + zv[j] * hb;
            }
            float2 o; o.x = hn[0]; o.y = hn[1];
            *(float2*)&out[((size_t)gb * TT + t) * HID + j0 + ec0] = o;
            g_hb[(size_t)gb * 512 + ((j0 + ec0) >> 1)] = pack_bf16(hn[0], hn[1]);
            if (t == TT - 1)
                *(float2*)&out[(size_t)BSZ * TT * HID + (size_t)gb * HID + j0 + ec0] = o;
        }

        if (t + 1 < TT)
            swsync(bcnt, bgen, 64);   // h complete (this half only)
    }
}

// =====================================================================
extern "C" void kernel_launch(void* const* d_in, const int* in_sizes, int n_in,
                              void* d_out, int out_size)
{
    const float* x  = (const float*)d_in[0];
    const float* h0 = (const float*)d_in[1];
    const float* wz = (const float*)d_in[2];
    const float* wr = (const float*)d_in[3];
    const float* wh = (const float*)d_in[4];
    const float* bz = (const float*)d_in[5];
    const float* br = (const float*)d_in[6];
    const float* bh = (const float*)d_in[7];
    float* out = (float*)d_out;

    const int x_smem = 4 * 64 * XS * sizeof(float);
    const int r_smem = (32 * AST2 + 8 * REDW + 32 * SFS) * sizeof(float);
    static bool attr_set = false;
    if (!attr_set) {
        cudaFuncSetAttribute(xproj_kernel,
                             cudaFuncAttributeMaxDynamicSharedMemorySize, x_smem);
        cudaFuncSetAttribute(recur_kernel,
                             cudaFuncAttributeMaxDynamicSharedMemorySize, r_smem);
        attr_set = true;
    }

    const int ysplit[4] = {0, 171, 342, 512};
    for (int s = 0; s < 3; s++) {
        dim3 g1(H3 / 64, ysplit[s + 1] - ysplit[s]);
        xproj_kernel<<<g1, 256, x_smem>>>(x, wz, wr, wh, bz, br, bh, ysplit[s]);
    }

    recur_kernel<<<128, 256, r_smem>>>(h0, wz, wr, wh, out);
}